// round 1
// baseline (speedup 1.0000x reference)
#include <cuda_runtime.h>
#include <math.h>
#include <stdint.h>

// ---------------------------------------------------------------------------
// Problem constants
// ---------------------------------------------------------------------------
constexpr int BB = 2;     // batch
constexpr int SS = 1024;  // seq len
constexpr int DD = 1024;  // model dim
constexpr int HH = 16;    // heads
constexpr int LL = 6;     // layers
constexpr int VV = 256;   // vocab
constexpr int HD = 64;    // head dim
constexpr int DF = 512;   // ffn dim
constexpr float ATT_SCALE = 0.125f;  // 1/sqrt(64)

// ---------------------------------------------------------------------------
// Scratch (static device globals -- no allocations allowed)
// ---------------------------------------------------------------------------
__device__ float g_h   [BB * SS * DD];
__device__ float g_q   [BB * SS * DD];
__device__ float g_k   [BB * SS * DD];
__device__ float g_v   [BB * SS * DD];
__device__ float g_attn[BB * SS * DD];
__device__ float g_t1  [BB * SS * DD];
__device__ float g_ff  [BB * SS * DF];
__device__ float g_qe  [(size_t)BB * HH * SS * SS];   // 134 MB
__device__ float g_lg  [(size_t)BB * HH * SS * SS];   // 134 MB

// ---------------------------------------------------------------------------
// Embedding + sinusoidal positional encoding
//   h[b,s,:] = emb[x[b,s],:] * 32 + pe[s,:]
// pe computed with double-precision phase range-reduction so the result is
// accurate whether or not fast-math rewrites sinf.
// ---------------------------------------------------------------------------
__global__ void embed_kernel(const int* __restrict__ x,
                             const float* __restrict__ emb,
                             float* __restrict__ h)
{
    const int bs = blockIdx.x;            // 0..B*S-1
    const int s  = bs & (SS - 1);
    const int tok = x[bs];
    const float* e = emb + (size_t)tok * DD;
    float* hp = h + (size_t)bs * DD;
    const double LN1E4 = 9.210340371976184;  // ln(1e4)
    for (int d = threadIdx.x; d < DD; d += blockDim.x) {
        const int par = d & 1;
        // match reference: two separate f32 exps, multiplied in f32
        const float r1 = (float)exp(-LN1E4 * (double)d   / 1024.0);
        const float r2 = (float)exp( LN1E4 * (double)par / 1024.0);
        const float rate = r1 * r2;
        const float ph = (float)s * rate + 1.5707964f * (float)par;
        const double rr = remainder((double)ph, 6.283185307179586);
        hp[d] = e[d] * 32.0f + sinf((float)rr);
    }
}

// ---------------------------------------------------------------------------
// Generic fp32 GEMM: C = A @ B (+bias) (+relu), optional B transpose.
// 64x64 tile, BK=16, 256 threads, 4x4 register micro-tile.
// Batched via blockIdx.z: z -> (zb = z/zdiv, zh = z%zdiv), pointer offsets
// A += zb*sA1 + zh*sA2 (same for B, C). All dims assumed multiples of tile.
// B tile in SMEM is XOR-swizzled so the transposed-B store path is
// (mostly) bank-conflict-free while keeping 16B-aligned float4 frag loads.
// ---------------------------------------------------------------------------
#define BSWZ(k, n) ((n) ^ (((k) & 15) << 2))

template<bool TRANSB, bool RELU>
__global__ __launch_bounds__(256)
void gemm_f32(const float* __restrict__ A, const float* __restrict__ Bm,
              const float* __restrict__ bias, float* __restrict__ C,
              int K, int lda, int ldb, int ldc, int zdiv,
              long long sA1, long long sA2,
              long long sB1, long long sB2,
              long long sC1, long long sC2)
{
    __shared__ float As[64][17];                     // [m][k], padded
    __shared__ __align__(16) float Bs[16][64];       // [k][n], swizzled

    const int tid = threadIdx.x;
    const int tx = tid & 15;        // output col group
    const int ty = tid >> 4;        // output row group
    const int m0 = blockIdx.y * 64;
    const int n0 = blockIdx.x * 64;

    const int z  = blockIdx.z;
    const int zb = z / zdiv;
    const int zh = z % zdiv;
    A  += (size_t)zb * sA1 + (size_t)zh * sA2;
    Bm += (size_t)zb * sB1 + (size_t)zh * sB2;
    C  += (size_t)zb * sC1 + (size_t)zh * sC2;

    float acc[4][4];
#pragma unroll
    for (int i = 0; i < 4; i++)
#pragma unroll
        for (int j = 0; j < 4; j++) acc[i][j] = 0.f;

    const int ac = tid & 15;   // k (A load) / k (BT load)
    const int ar = tid >> 4;   // row base (A load / BT load)
    const int bn = tid & 63;   // n (B no-trans load)
    const int bk = tid >> 6;   // k base (B no-trans load)

    for (int k0 = 0; k0 < K; k0 += 16) {
#pragma unroll
        for (int i = 0; i < 4; i++) {
            const int m = ar + i * 16;
            As[m][ac] = A[(size_t)(m0 + m) * lda + (k0 + ac)];
        }
        if (!TRANSB) {
#pragma unroll
            for (int i = 0; i < 4; i++) {
                const int kk = bk + i * 4;
                Bs[kk][BSWZ(kk, bn)] = Bm[(size_t)(k0 + kk) * ldb + (n0 + bn)];
            }
        } else {
#pragma unroll
            for (int i = 0; i < 4; i++) {
                const int n = ar + i * 16;
                Bs[ac][BSWZ(ac, n)] = Bm[(size_t)(n0 + n) * ldb + (k0 + ac)];
            }
        }
        __syncthreads();
#pragma unroll
        for (int kk = 0; kk < 16; kk++) {
            const float4 bv = *(const float4*)&Bs[kk][BSWZ(kk, tx * 4)];
            const float a0 = As[ty * 4 + 0][kk];
            const float a1 = As[ty * 4 + 1][kk];
            const float a2 = As[ty * 4 + 2][kk];
            const float a3 = As[ty * 4 + 3][kk];
            acc[0][0] += a0 * bv.x; acc[0][1] += a0 * bv.y;
            acc[0][2] += a0 * bv.z; acc[0][3] += a0 * bv.w;
            acc[1][0] += a1 * bv.x; acc[1][1] += a1 * bv.y;
            acc[1][2] += a1 * bv.z; acc[1][3] += a1 * bv.w;
            acc[2][0] += a2 * bv.x; acc[2][1] += a2 * bv.y;
            acc[2][2] += a2 * bv.z; acc[2][3] += a2 * bv.w;
            acc[3][0] += a3 * bv.x; acc[3][1] += a3 * bv.y;
            acc[3][2] += a3 * bv.z; acc[3][3] += a3 * bv.w;
        }
        __syncthreads();
    }

    float bvals[4] = {0.f, 0.f, 0.f, 0.f};
    if (bias) {
#pragma unroll
        for (int j = 0; j < 4; j++) bvals[j] = bias[n0 + tx * 4 + j];
    }
#pragma unroll
    for (int i = 0; i < 4; i++) {
#pragma unroll
        for (int j = 0; j < 4; j++) {
            float vo = acc[i][j] + bvals[j];
            if (RELU) vo = fmaxf(vo, 0.f);
            C[(size_t)(m0 + ty * 4 + i) * ldc + (n0 + tx * 4 + j)] = vo;
        }
    }
}

// ---------------------------------------------------------------------------
// Fused: Srel gather (analytic skew) + scale + causal/pad mask + softmax.
// Skew identity: Srel[i,j] = QE[i, S-1-i+j] for j<=i, else 0.
// One block per (b,h,i) row; in-place on the logits buffer.
// ---------------------------------------------------------------------------
__global__ __launch_bounds__(256)
void attn_softmax(float* __restrict__ lg, const float* __restrict__ qe,
                  const int* __restrict__ x)
{
    const int i  = blockIdx.x;
    const int bh = blockIdx.y;
    const int b  = bh >> 4;   // /HH
    float* row        = lg + (size_t)bh * SS * SS + (size_t)i * SS;
    const float* qrow = qe + (size_t)bh * SS * SS + (size_t)i * SS;
    const int* xb = x + b * SS;
    const int t = threadIdx.x;

    float vals[4];
    float mx = -1e30f;
#pragma unroll
    for (int c = 0; c < 4; c++) {
        const int j = t + c * 256;
        float vv = row[j];
        if (j <= i) vv += qrow[SS - 1 - i + j];
        vv *= ATT_SCALE;
        if (j > i || xb[j] == 0) vv -= 1e9f;
        vals[c] = vv;
        mx = fmaxf(mx, vv);
    }
    __shared__ float sh[8];
#pragma unroll
    for (int o = 16; o > 0; o >>= 1) mx = fmaxf(mx, __shfl_xor_sync(0xffffffffu, mx, o));
    if ((t & 31) == 0) sh[t >> 5] = mx;
    __syncthreads();
    mx = sh[0];
#pragma unroll
    for (int w = 1; w < 8; w++) mx = fmaxf(mx, sh[w]);

    float s = 0.f;
#pragma unroll
    for (int c = 0; c < 4; c++) { vals[c] = expf(vals[c] - mx); s += vals[c]; }
#pragma unroll
    for (int o = 16; o > 0; o >>= 1) s += __shfl_xor_sync(0xffffffffu, s, o);
    __syncthreads();
    if ((t & 31) == 0) sh[t >> 5] = s;
    __syncthreads();
    s = 0.f;
#pragma unroll
    for (int w = 0; w < 8; w++) s += sh[w];
    const float inv = 1.f / s;
#pragma unroll
    for (int c = 0; c < 4; c++) row[t + c * 256] = vals[c] * inv;
}

// ---------------------------------------------------------------------------
// LayerNorm over last dim (1024), in place. One block per row.
// ---------------------------------------------------------------------------
__global__ __launch_bounds__(256)
void ln_kernel(float* __restrict__ xio, const float* __restrict__ g,
               const float* __restrict__ be)
{
    const int row = blockIdx.x;
    float* p = xio + (size_t)row * DD;
    const int t = threadIdx.x;
    float v[4];
    float s = 0.f, s2 = 0.f;
#pragma unroll
    for (int c = 0; c < 4; c++) {
        v[c] = p[t + c * 256];
        s += v[c];
        s2 += v[c] * v[c];
    }
    __shared__ float sh1[8], sh2[8];
#pragma unroll
    for (int o = 16; o > 0; o >>= 1) {
        s  += __shfl_xor_sync(0xffffffffu, s,  o);
        s2 += __shfl_xor_sync(0xffffffffu, s2, o);
    }
    if ((t & 31) == 0) { sh1[t >> 5] = s; sh2[t >> 5] = s2; }
    __syncthreads();
    s = 0.f; s2 = 0.f;
#pragma unroll
    for (int w = 0; w < 8; w++) { s += sh1[w]; s2 += sh2[w]; }
    const float mu  = s  * (1.f / DD);
    const float var = s2 * (1.f / DD) - mu * mu;
    const float inv = rsqrtf(var + 1e-6f);
#pragma unroll
    for (int c = 0; c < 4; c++) {
        const int d = t + c * 256;
        p[d] = (v[c] - mu) * inv * g[d] + be[d];
    }
}

// ---------------------------------------------------------------------------
// Host-side launch helper
// ---------------------------------------------------------------------------
template<bool TRANSB, bool RELU>
static void run_gemm(const float* A, const float* Bm, const float* bias, float* C,
                     int M, int N, int K, int lda, int ldb, int ldc,
                     int batch, int zdiv,
                     long long sA1, long long sA2,
                     long long sB1, long long sB2,
                     long long sC1, long long sC2)
{
    dim3 grid(N / 64, M / 64, batch);
    gemm_f32<TRANSB, RELU><<<grid, 256>>>(A, Bm, bias, C, K, lda, ldb, ldc,
                                          zdiv, sA1, sA2, sB1, sB2, sC1, sC2);
}

extern "C" void kernel_launch(void* const* d_in, const int* in_sizes, int n_in,
                              void* d_out, int out_size)
{
    const int*   x   = (const int*)  d_in[0];
    const float* emb = (const float*)d_in[1];
    const float* Wq  = (const float*)d_in[2];
    const float* bq  = (const float*)d_in[3];
    const float* Wk  = (const float*)d_in[4];
    const float* bk  = (const float*)d_in[5];
    const float* Wv  = (const float*)d_in[6];
    const float* bv  = (const float*)d_in[7];
    const float* Wo  = (const float*)d_in[8];
    const float* bo  = (const float*)d_in[9];
    const float* W1  = (const float*)d_in[10];
    const float* b1  = (const float*)d_in[11];
    const float* W2  = (const float*)d_in[12];
    const float* b2  = (const float*)d_in[13];
    const float* g1  = (const float*)d_in[14];
    const float* be1 = (const float*)d_in[15];
    const float* g2  = (const float*)d_in[16];
    const float* be2 = (const float*)d_in[17];
    const float* E   = (const float*)d_in[18];
    const float* Wf  = (const float*)d_in[19];
    const float* bf  = (const float*)d_in[20];
    float* out = (float*)d_out;

    float *h, *q, *k, *v, *at, *t1, *ff, *qe, *lg;
    cudaGetSymbolAddress((void**)&h,  g_h);
    cudaGetSymbolAddress((void**)&q,  g_q);
    cudaGetSymbolAddress((void**)&k,  g_k);
    cudaGetSymbolAddress((void**)&v,  g_v);
    cudaGetSymbolAddress((void**)&at, g_attn);
    cudaGetSymbolAddress((void**)&t1, g_t1);
    cudaGetSymbolAddress((void**)&ff, g_ff);
    cudaGetSymbolAddress((void**)&qe, g_qe);
    cudaGetSymbolAddress((void**)&lg, g_lg);

    const int M = BB * SS;  // 2048 token rows
    const long long sSD  = (long long)SS * DD;
    const long long sHSS = (long long)HH * SS * SS;
    const long long sSSq = (long long)SS * SS;

    embed_kernel<<<BB * SS, 256>>>(x, emb, h);

    for (int l = 0; l < LL; l++) {
        const float* Wql = Wq + (size_t)l * DD * DD;
        const float* Wkl = Wk + (size_t)l * DD * DD;
        const float* Wvl = Wv + (size_t)l * DD * DD;
        const float* Wol = Wo + (size_t)l * DD * DD;
        const float* W1l = W1 + (size_t)l * DD * DF;
        const float* W2l = W2 + (size_t)l * DF * DD;
        const float* El  = E  + (size_t)l * SS * HD;

        // Q/K/V projections: [2048,1024] @ [1024,1024] + bias
        run_gemm<false, false>(h, Wql, bq + l * DD, q, M, DD, DD, DD, DD, DD,
                               1, 1, 0, 0, 0, 0, 0, 0);
        run_gemm<false, false>(h, Wkl, bk + l * DD, k, M, DD, DD, DD, DD, DD,
                               1, 1, 0, 0, 0, 0, 0, 0);
        run_gemm<false, false>(h, Wvl, bv + l * DD, v, M, DD, DD, DD, DD, DD,
                               1, 1, 0, 0, 0, 0, 0, 0);

        // QE[b,h] = q_bh @ E_l^T : batched NT, [1024,64] @ [64,1024]
        run_gemm<true, false>(q, El, nullptr, qe, SS, SS, HD, DD, HD, SS,
                              BB * HH, HH,
                              sSD, HD,          // A offsets (b,h)
                              0, 0,             // E shared
                              sHSS, sSSq);      // C offsets
        // QK^T: batched NT
        run_gemm<true, false>(q, k, nullptr, lg, SS, SS, HD, DD, DD, SS,
                              BB * HH, HH,
                              sSD, HD,
                              sSD, HD,
                              sHSS, sSSq);

        // fused skew + masks + softmax (in place on lg)
        attn_softmax<<<dim3(SS, BB * HH), 256>>>(lg, qe, x);

        // attn = aw @ v : batched NN, [1024,1024] @ [1024,64]
        run_gemm<false, false>(lg, v, nullptr, at, SS, HD, SS, SS, DD, DD,
                               BB * HH, HH,
                               sHSS, sSSq,
                               sSD, HD,
                               sSD, HD);

        // output projection + LN1
        run_gemm<false, false>(at, Wol, bo + l * DD, t1, M, DD, DD, DD, DD, DD,
                               1, 1, 0, 0, 0, 0, 0, 0);
        ln_kernel<<<BB * SS, 256>>>(t1, g1 + l * DD, be1 + l * DD);

        // FFN: relu(o1 @ W1 + b1) @ W2 + b2, then LN2 -> h
        run_gemm<false, true>(t1, W1l, b1 + l * DF, ff, M, DF, DD, DD, DF, DF,
                              1, 1, 0, 0, 0, 0, 0, 0);
        run_gemm<false, false>(ff, W2l, b2 + l * DD, h, M, DD, DF, DF, DD, DD,
                               1, 1, 0, 0, 0, 0, 0, 0);
        ln_kernel<<<BB * SS, 256>>>(h, g2 + l * DD, be2 + l * DD);
    }

    // final projection to vocab: [2048,1024] @ [1024,256] + bf
    run_gemm<false, false>(h, Wf, bf, out, M, VV, DD, DD, VV, VV,
                           1, 1, 0, 0, 0, 0, 0, 0);
}

// round 2
// speedup vs baseline: 1.4918x; 1.4918x over previous
#include <cuda_runtime.h>
#include <math.h>
#include <stdint.h>

// ---------------------------------------------------------------------------
// Problem constants
// ---------------------------------------------------------------------------
constexpr int BB = 2;     // batch
constexpr int SS = 1024;  // seq len
constexpr int DD = 1024;  // model dim
constexpr int HH = 16;    // heads
constexpr int LL = 6;     // layers
constexpr int VV = 256;   // vocab
constexpr int HD = 64;    // head dim
constexpr int DF = 512;   // ffn dim
constexpr float ATT_SCALE = 0.125f;  // 1/sqrt(64)

// ---------------------------------------------------------------------------
// Scratch (static device globals -- no allocations allowed)
// ---------------------------------------------------------------------------
__device__ float g_h   [BB * SS * DD];
__device__ float g_q   [BB * SS * DD];
__device__ float g_k   [BB * SS * DD];
__device__ float g_v   [BB * SS * DD];
__device__ float g_attn[BB * SS * DD];
__device__ float g_t1  [BB * SS * DD];
__device__ float g_ff  [BB * SS * DF];
__device__ float g_qe  [(size_t)BB * HH * SS * SS];   // 134 MB
__device__ float g_lg  [(size_t)BB * HH * SS * SS];   // 134 MB
__device__ float g_rate[DD];

// ---------------------------------------------------------------------------
// Precompute sinusoid rate[d] (the only place fp64 is needed, 1024 lanes once)
// ---------------------------------------------------------------------------
__global__ void rate_kernel(float* __restrict__ rate)
{
    const int d = blockIdx.x * 256 + threadIdx.x;
    if (d >= DD) return;
    const double LN1E4 = 9.210340371976184;  // ln(1e4)
    const int par = d & 1;
    const float r1 = (float)exp(-LN1E4 * (double)d   / 1024.0);
    const float r2 = (float)exp( LN1E4 * (double)par / 1024.0);
    rate[d] = r1 * r2;
}

// ---------------------------------------------------------------------------
// Embedding + sinusoidal positional encoding (all fp32 now)
// ---------------------------------------------------------------------------
__global__ void embed_kernel(const int* __restrict__ x,
                             const float* __restrict__ emb,
                             const float* __restrict__ rate,
                             float* __restrict__ h)
{
    const int bs = blockIdx.x;            // 0..B*S-1
    const int s  = bs & (SS - 1);
    const int tok = x[bs];
    const float* e = emb + (size_t)tok * DD;
    float* hp = h + (size_t)bs * DD;
    for (int d = threadIdx.x; d < DD; d += blockDim.x) {
        const int par = d & 1;
        const float ph = (float)s * rate[d] + 1.5707964f * (float)par;
        hp[d] = e[d] * 32.0f + sinf(ph);
    }
}

// ---------------------------------------------------------------------------
// 128x128x8 fp32 GEMM, 256 threads, 8x8 micro-tile (2x2 float4 quadrants),
// global->register prefetch. Optional B transpose, bias, relu.
// SKIP: 0=none, 1=QE lower-left skip, 2=strictly-upper skip (causal).
// Batched via blockIdx.z like before.
// ---------------------------------------------------------------------------
template<bool TRANSB, bool RELU, int SKIP>
__global__ __launch_bounds__(256, 2)
void gemm128(const float* __restrict__ A, const float* __restrict__ Bm,
             const float* __restrict__ bias, float* __restrict__ C,
             int K, int lda, int ldb, int ldc, int zdiv,
             long long sA1, long long sA2,
             long long sB1, long long sB2,
             long long sC1, long long sC2)
{
    const int m0 = blockIdx.y * 128;
    const int n0 = blockIdx.x * 128;
    if (SKIP == 1 && (m0 + n0 + 254 < SS - 1)) return;   // QE: unused lower-left
    if (SKIP == 2 && (n0 >= m0 + 128)) return;           // QK: strictly future

    __shared__ __align__(16) float As[8][128];
    __shared__ __align__(16) float Bs[8][128];

    const int tid = threadIdx.x;
    const int tx = tid & 15;
    const int ty = tid >> 4;

    const int z  = blockIdx.z;
    const int zb = z / zdiv;
    const int zh = z % zdiv;
    A  += (size_t)zb * sA1 + (size_t)zh * sA2;
    Bm += (size_t)zb * sB1 + (size_t)zh * sB2;
    C  += (size_t)zb * sC1 + (size_t)zh * sC2;

    // loader coordinates
    const int arow = tid >> 1;           // 0..127
    const int acol = (tid & 1) * 4;      // 0 or 4
    const int brow = tid >> 5;           // 0..7   (NN)
    const int bcol = (tid & 31) * 4;     // 0..124 (NN)
    const int tbn  = tid >> 1;           // 0..127 (TB)
    const int tbk  = (tid & 1) * 4;      // 0 or 4 (TB)

    float acc[8][8];
#pragma unroll
    for (int i = 0; i < 8; i++)
#pragma unroll
        for (int j = 0; j < 8; j++) acc[i][j] = 0.f;

    const float* Ap = A + (size_t)(m0 + arow) * lda + acol;

    float4 pa, pb;
    pa = *(const float4*)&Ap[0];
    if (!TRANSB) pb = *(const float4*)&Bm[(size_t)brow * ldb + n0 + bcol];
    else         pb = *(const float4*)&Bm[(size_t)(n0 + tbn) * ldb + tbk];

    for (int k0 = 0; k0 < K; k0 += 8) {
        // stage prefetched tile into smem
        As[acol + 0][arow] = pa.x;
        As[acol + 1][arow] = pa.y;
        As[acol + 2][arow] = pa.z;
        As[acol + 3][arow] = pa.w;
        if (!TRANSB) {
            *(float4*)&Bs[brow][bcol] = pb;
        } else {
            Bs[tbk + 0][tbn] = pb.x;
            Bs[tbk + 1][tbn] = pb.y;
            Bs[tbk + 2][tbn] = pb.z;
            Bs[tbk + 3][tbn] = pb.w;
        }
        __syncthreads();

        if (k0 + 8 < K) {
            pa = *(const float4*)&Ap[k0 + 8];
            if (!TRANSB) pb = *(const float4*)&Bm[(size_t)(k0 + 8 + brow) * ldb + n0 + bcol];
            else         pb = *(const float4*)&Bm[(size_t)(n0 + tbn) * ldb + k0 + 8 + tbk];
        }

#pragma unroll
        for (int kk = 0; kk < 8; kk++) {
            const float4 a0 = *(const float4*)&As[kk][ty * 4];
            const float4 a1 = *(const float4*)&As[kk][64 + ty * 4];
            const float4 b0 = *(const float4*)&Bs[kk][tx * 4];
            const float4 b1 = *(const float4*)&Bs[kk][64 + tx * 4];
            const float ar[8] = {a0.x, a0.y, a0.z, a0.w, a1.x, a1.y, a1.z, a1.w};
            const float br[8] = {b0.x, b0.y, b0.z, b0.w, b1.x, b1.y, b1.z, b1.w};
#pragma unroll
            for (int i = 0; i < 8; i++)
#pragma unroll
                for (int j = 0; j < 8; j++)
                    acc[i][j] += ar[i] * br[j];
        }
        __syncthreads();
    }

    float bv[8] = {0, 0, 0, 0, 0, 0, 0, 0};
    if (bias) {
#pragma unroll
        for (int j = 0; j < 4; j++) {
            bv[j]     = bias[n0 + tx * 4 + j];
            bv[4 + j] = bias[n0 + 64 + tx * 4 + j];
        }
    }
#pragma unroll
    for (int rq = 0; rq < 2; rq++) {
#pragma unroll
        for (int i = 0; i < 4; i++) {
            const int r = m0 + rq * 64 + ty * 4 + i;
            float4 o0, o1;
            o0.x = acc[rq * 4 + i][0] + bv[0];
            o0.y = acc[rq * 4 + i][1] + bv[1];
            o0.z = acc[rq * 4 + i][2] + bv[2];
            o0.w = acc[rq * 4 + i][3] + bv[3];
            o1.x = acc[rq * 4 + i][4] + bv[4];
            o1.y = acc[rq * 4 + i][5] + bv[5];
            o1.z = acc[rq * 4 + i][6] + bv[6];
            o1.w = acc[rq * 4 + i][7] + bv[7];
            if (RELU) {
                o0.x = fmaxf(o0.x, 0.f); o0.y = fmaxf(o0.y, 0.f);
                o0.z = fmaxf(o0.z, 0.f); o0.w = fmaxf(o0.w, 0.f);
                o1.x = fmaxf(o1.x, 0.f); o1.y = fmaxf(o1.y, 0.f);
                o1.z = fmaxf(o1.z, 0.f); o1.w = fmaxf(o1.w, 0.f);
            }
            *(float4*)&C[(size_t)r * ldc + n0 + tx * 4]      = o0;
            *(float4*)&C[(size_t)r * ldc + n0 + 64 + tx * 4] = o1;
        }
    }
}

// ---------------------------------------------------------------------------
// 64x64x16 fp32 GEMM (kept for the N=64 AV GEMM). KCAP bounds the K loop to
// the causal region (aw is exactly 0 beyond it).
// ---------------------------------------------------------------------------
#define BSWZ(k, n) ((n) ^ (((k) & 15) << 2))

template<bool RELU, bool KCAP>
__global__ __launch_bounds__(256)
void gemm64(const float* __restrict__ A, const float* __restrict__ Bm,
            const float* __restrict__ bias, float* __restrict__ C,
            int K, int lda, int ldb, int ldc, int zdiv,
            long long sA1, long long sA2,
            long long sB1, long long sB2,
            long long sC1, long long sC2)
{
    __shared__ float As[64][17];
    __shared__ __align__(16) float Bs[16][64];

    const int tid = threadIdx.x;
    const int tx = tid & 15;
    const int ty = tid >> 4;
    const int m0 = blockIdx.y * 64;
    const int n0 = blockIdx.x * 64;

    const int z  = blockIdx.z;
    const int zb = z / zdiv;
    const int zh = z % zdiv;
    A  += (size_t)zb * sA1 + (size_t)zh * sA2;
    Bm += (size_t)zb * sB1 + (size_t)zh * sB2;
    C  += (size_t)zb * sC1 + (size_t)zh * sC2;

    float acc[4][4];
#pragma unroll
    for (int i = 0; i < 4; i++)
#pragma unroll
        for (int j = 0; j < 4; j++) acc[i][j] = 0.f;

    const int ac = tid & 15;
    const int ar = tid >> 4;
    const int bn = tid & 63;
    const int bk = tid >> 6;

    const int Keff = KCAP ? min(K, m0 + 64) : K;

    for (int k0 = 0; k0 < Keff; k0 += 16) {
#pragma unroll
        for (int i = 0; i < 4; i++) {
            const int m = ar + i * 16;
            As[m][ac] = A[(size_t)(m0 + m) * lda + (k0 + ac)];
        }
#pragma unroll
        for (int i = 0; i < 4; i++) {
            const int kk = bk + i * 4;
            Bs[kk][BSWZ(kk, bn)] = Bm[(size_t)(k0 + kk) * ldb + (n0 + bn)];
        }
        __syncthreads();
#pragma unroll
        for (int kk = 0; kk < 16; kk++) {
            const float4 bvv = *(const float4*)&Bs[kk][BSWZ(kk, tx * 4)];
            const float a0 = As[ty * 4 + 0][kk];
            const float a1 = As[ty * 4 + 1][kk];
            const float a2 = As[ty * 4 + 2][kk];
            const float a3 = As[ty * 4 + 3][kk];
            acc[0][0] += a0 * bvv.x; acc[0][1] += a0 * bvv.y;
            acc[0][2] += a0 * bvv.z; acc[0][3] += a0 * bvv.w;
            acc[1][0] += a1 * bvv.x; acc[1][1] += a1 * bvv.y;
            acc[1][2] += a1 * bvv.z; acc[1][3] += a1 * bvv.w;
            acc[2][0] += a2 * bvv.x; acc[2][1] += a2 * bvv.y;
            acc[2][2] += a2 * bvv.z; acc[2][3] += a2 * bvv.w;
            acc[3][0] += a3 * bvv.x; acc[3][1] += a3 * bvv.y;
            acc[3][2] += a3 * bvv.z; acc[3][3] += a3 * bvv.w;
        }
        __syncthreads();
    }

    float bvals[4] = {0.f, 0.f, 0.f, 0.f};
    if (bias) {
#pragma unroll
        for (int j = 0; j < 4; j++) bvals[j] = bias[n0 + tx * 4 + j];
    }
#pragma unroll
    for (int i = 0; i < 4; i++) {
#pragma unroll
        for (int j = 0; j < 4; j++) {
            float vo = acc[i][j] + bvals[j];
            if (RELU) vo = fmaxf(vo, 0.f);
            C[(size_t)(m0 + ty * 4 + i) * ldc + (n0 + tx * 4 + j)] = vo;
        }
    }
}

// ---------------------------------------------------------------------------
// Fused Srel gather + scale + causal/pad mask + softmax, causal-truncated.
// Only chunks of 256 cols with base <= i are read/written; everything beyond
// is exactly 0 in the reference softmax (guaranteed when x[b,0] != 0).
// ---------------------------------------------------------------------------
__global__ __launch_bounds__(256)
void attn_softmax(float* __restrict__ lg, const float* __restrict__ qe,
                  const int* __restrict__ x)
{
    const int i  = blockIdx.x;
    const int bh = blockIdx.y;
    const int b  = bh >> 4;
    float* row        = lg + (size_t)bh * SS * SS + (size_t)i * SS;
    const float* qrow = qe + (size_t)bh * SS * SS + (size_t)i * SS;
    const int* xb = x + b * SS;
    const int t = threadIdx.x;
    const int nch = (i >> 8) + 1;

    float vals[4];
    float mx = -1e30f;
    for (int c = 0; c < nch; c++) {
        const int j = c * 256 + t;
        float vv = -1e30f;
        if (j <= i) {
            vv = (row[j] + qrow[SS - 1 - i + j]) * ATT_SCALE;
            if (xb[j] == 0) vv -= 1e9f;
        }
        vals[c] = vv;
        mx = fmaxf(mx, vv);
    }
    __shared__ float sh[8];
#pragma unroll
    for (int o = 16; o > 0; o >>= 1) mx = fmaxf(mx, __shfl_xor_sync(0xffffffffu, mx, o));
    if ((t & 31) == 0) sh[t >> 5] = mx;
    __syncthreads();
    mx = sh[0];
#pragma unroll
    for (int w = 1; w < 8; w++) mx = fmaxf(mx, sh[w]);

    float s = 0.f;
    for (int c = 0; c < nch; c++) { vals[c] = expf(vals[c] - mx); s += vals[c]; }
#pragma unroll
    for (int o = 16; o > 0; o >>= 1) s += __shfl_xor_sync(0xffffffffu, s, o);
    __syncthreads();
    if ((t & 31) == 0) sh[t >> 5] = s;
    __syncthreads();
    s = 0.f;
#pragma unroll
    for (int w = 0; w < 8; w++) s += sh[w];
    const float inv = 1.f / s;
    for (int c = 0; c < nch; c++) row[c * 256 + t] = vals[c] * inv;
}

// ---------------------------------------------------------------------------
// LayerNorm over last dim (1024), in place. One block per row.
// ---------------------------------------------------------------------------
__global__ __launch_bounds__(256)
void ln_kernel(float* __restrict__ xio, const float* __restrict__ g,
               const float* __restrict__ be)
{
    const int row = blockIdx.x;
    float* p = xio + (size_t)row * DD;
    const int t = threadIdx.x;
    float v[4];
    float s = 0.f, s2 = 0.f;
#pragma unroll
    for (int c = 0; c < 4; c++) {
        v[c] = p[t + c * 256];
        s += v[c];
        s2 += v[c] * v[c];
    }
    __shared__ float sh1[8], sh2[8];
#pragma unroll
    for (int o = 16; o > 0; o >>= 1) {
        s  += __shfl_xor_sync(0xffffffffu, s,  o);
        s2 += __shfl_xor_sync(0xffffffffu, s2, o);
    }
    if ((t & 31) == 0) { sh1[t >> 5] = s; sh2[t >> 5] = s2; }
    __syncthreads();
    s = 0.f; s2 = 0.f;
#pragma unroll
    for (int w = 0; w < 8; w++) { s += sh1[w]; s2 += sh2[w]; }
    const float mu  = s  * (1.f / DD);
    const float var = s2 * (1.f / DD) - mu * mu;
    const float inv = rsqrtf(var + 1e-6f);
#pragma unroll
    for (int c = 0; c < 4; c++) {
        const int d = t + c * 256;
        p[d] = (v[c] - mu) * inv * g[d] + be[d];
    }
}

// ---------------------------------------------------------------------------
// Host-side launch helpers
// ---------------------------------------------------------------------------
template<bool TRANSB, bool RELU, int SKIP>
static void run_g128(const float* A, const float* Bm, const float* bias, float* C,
                     int M, int N, int K, int lda, int ldb, int ldc,
                     int batch, int zdiv,
                     long long sA1, long long sA2,
                     long long sB1, long long sB2,
                     long long sC1, long long sC2)
{
    dim3 grid(N / 128, M / 128, batch);
    gemm128<TRANSB, RELU, SKIP><<<grid, 256>>>(A, Bm, bias, C, K, lda, ldb, ldc,
                                               zdiv, sA1, sA2, sB1, sB2, sC1, sC2);
}

extern "C" void kernel_launch(void* const* d_in, const int* in_sizes, int n_in,
                              void* d_out, int out_size)
{
    const int*   x   = (const int*)  d_in[0];
    const float* emb = (const float*)d_in[1];
    const float* Wq  = (const float*)d_in[2];
    const float* bq  = (const float*)d_in[3];
    const float* Wk  = (const float*)d_in[4];
    const float* bk  = (const float*)d_in[5];
    const float* Wv  = (const float*)d_in[6];
    const float* bv  = (const float*)d_in[7];
    const float* Wo  = (const float*)d_in[8];
    const float* bo  = (const float*)d_in[9];
    const float* W1  = (const float*)d_in[10];
    const float* b1  = (const float*)d_in[11];
    const float* W2  = (const float*)d_in[12];
    const float* b2  = (const float*)d_in[13];
    const float* g1  = (const float*)d_in[14];
    const float* be1 = (const float*)d_in[15];
    const float* g2  = (const float*)d_in[16];
    const float* be2 = (const float*)d_in[17];
    const float* E   = (const float*)d_in[18];
    const float* Wf  = (const float*)d_in[19];
    const float* bf  = (const float*)d_in[20];
    float* out = (float*)d_out;

    float *h, *q, *k, *v, *at, *t1, *ff, *qe, *lg, *rate;
    cudaGetSymbolAddress((void**)&h,  g_h);
    cudaGetSymbolAddress((void**)&q,  g_q);
    cudaGetSymbolAddress((void**)&k,  g_k);
    cudaGetSymbolAddress((void**)&v,  g_v);
    cudaGetSymbolAddress((void**)&at, g_attn);
    cudaGetSymbolAddress((void**)&t1, g_t1);
    cudaGetSymbolAddress((void**)&ff, g_ff);
    cudaGetSymbolAddress((void**)&qe, g_qe);
    cudaGetSymbolAddress((void**)&lg, g_lg);
    cudaGetSymbolAddress((void**)&rate, g_rate);

    const int M = BB * SS;  // 2048 token rows
    const long long sSD  = (long long)SS * DD;
    const long long sHSS = (long long)HH * SS * SS;
    const long long sSSq = (long long)SS * SS;

    rate_kernel<<<4, 256>>>(rate);
    embed_kernel<<<BB * SS, 256>>>(x, emb, rate, h);

    for (int l = 0; l < LL; l++) {
        const float* Wql = Wq + (size_t)l * DD * DD;
        const float* Wkl = Wk + (size_t)l * DD * DD;
        const float* Wvl = Wv + (size_t)l * DD * DD;
        const float* Wol = Wo + (size_t)l * DD * DD;
        const float* W1l = W1 + (size_t)l * DD * DF;
        const float* W2l = W2 + (size_t)l * DF * DD;
        const float* El  = E  + (size_t)l * SS * HD;

        // Q/K/V projections: [2048,1024] @ [1024,1024] + bias
        run_g128<false, false, 0>(h, Wql, bq + l * DD, q, M, DD, DD, DD, DD, DD,
                                  1, 1, 0, 0, 0, 0, 0, 0);
        run_g128<false, false, 0>(h, Wkl, bk + l * DD, k, M, DD, DD, DD, DD, DD,
                                  1, 1, 0, 0, 0, 0, 0, 0);
        run_g128<false, false, 0>(h, Wvl, bv + l * DD, v, M, DD, DD, DD, DD, DD,
                                  1, 1, 0, 0, 0, 0, 0, 0);

        // QE[b,h] = q_bh @ E_l^T (lower-left tiles skipped)
        run_g128<true, false, 1>(q, El, nullptr, qe, SS, SS, HD, DD, HD, SS,
                                 BB * HH, HH,
                                 sSD, HD,
                                 0, 0,
                                 sHSS, sSSq);
        // QK^T (strictly-upper tiles skipped)
        run_g128<true, false, 2>(q, k, nullptr, lg, SS, SS, HD, DD, DD, SS,
                                 BB * HH, HH,
                                 sSD, HD,
                                 sSD, HD,
                                 sHSS, sSSq);

        // fused skew + masks + softmax (in place on lg, causal-truncated)
        attn_softmax<<<dim3(SS, BB * HH), 256>>>(lg, qe, x);

        // attn = aw @ v : batched NN, K capped at causal boundary
        {
            dim3 grid(HD / 64, SS / 64, BB * HH);
            gemm64<false, true><<<grid, 256>>>(lg, v, nullptr, at, SS, SS, DD, DD,
                                               HH,
                                               sHSS, sSSq,
                                               sSD, HD,
                                               sSD, HD);
        }

        // output projection + LN1
        run_g128<false, false, 0>(at, Wol, bo + l * DD, t1, M, DD, DD, DD, DD, DD,
                                  1, 1, 0, 0, 0, 0, 0, 0);
        ln_kernel<<<BB * SS, 256>>>(t1, g1 + l * DD, be1 + l * DD);

        // FFN: relu(o1 @ W1 + b1) @ W2 + b2, then LN2 -> h
        run_g128<false, true, 0>(t1, W1l, b1 + l * DF, ff, M, DF, DD, DD, DF, DF,
                                 1, 1, 0, 0, 0, 0, 0, 0);
        run_g128<false, false, 0>(ff, W2l, b2 + l * DD, h, M, DD, DF, DF, DD, DD,
                                  1, 1, 0, 0, 0, 0, 0, 0);
        ln_kernel<<<BB * SS, 256>>>(h, g2 + l * DD, be2 + l * DD);
    }

    // final projection to vocab: [2048,1024] @ [1024,256] + bf
    run_g128<false, false, 0>(h, Wf, bf, out, M, VV, DD, DD, VV, VV,
                              1, 1, 0, 0, 0, 0, 0, 0);
}

// round 4
// speedup vs baseline: 2.6174x; 1.7545x over previous
#include <cuda_runtime.h>
#include <cuda_bf16.h>
#include <math.h>
#include <stdint.h>

// ---------------------------------------------------------------------------
// Problem constants
// ---------------------------------------------------------------------------
constexpr int BB = 2;     // batch
constexpr int SS = 1024;  // seq len
constexpr int DD = 1024;  // model dim
constexpr int HH = 16;    // heads
constexpr int LL = 6;     // layers
constexpr int VV = 256;   // vocab
constexpr int HD = 64;    // head dim
constexpr int DF = 512;   // ffn dim
constexpr float ATT_SCALE = 0.125f;  // 1/sqrt(64)

// ---------------------------------------------------------------------------
// Scratch (static device globals -- no allocations allowed)
// ---------------------------------------------------------------------------
__device__ float g_h   [BB * SS * DD];
__device__ float g_q   [BB * SS * DD];
__device__ float g_k   [BB * SS * DD];
__device__ float g_v   [BB * SS * DD];
__device__ float g_attn[BB * SS * DD];
__device__ float g_t1  [BB * SS * DD];
__device__ float g_ff  [BB * SS * DF];
__device__ float g_qe  [(size_t)BB * HH * SS * SS];   // 134 MB
__device__ float g_lg  [(size_t)BB * HH * SS * SS];   // 134 MB
__device__ float g_rate[DD];

// bf16 split weight buffers ([N, K] transposed, hi/lo)
__device__ __nv_bfloat16 g_wq_h[LL * DD * DD], g_wq_l[LL * DD * DD];
__device__ __nv_bfloat16 g_wk_h[LL * DD * DD], g_wk_l[LL * DD * DD];
__device__ __nv_bfloat16 g_wv_h[LL * DD * DD], g_wv_l[LL * DD * DD];
__device__ __nv_bfloat16 g_wo_h[LL * DD * DD], g_wo_l[LL * DD * DD];
__device__ __nv_bfloat16 g_w1_h[LL * DF * DD], g_w1_l[LL * DF * DD];
__device__ __nv_bfloat16 g_w2_h[LL * DD * DF], g_w2_l[LL * DD * DF];
__device__ __nv_bfloat16 g_wf_h[VV * DD],      g_wf_l[VV * DD];
// bf16 split activation buffers
__device__ __nv_bfloat16 g_ah[BB * SS * DD], g_al[BB * SS * DD];

// ---------------------------------------------------------------------------
// PTX helpers (mma.sync / ldmatrix / cp.async -- standard ISA, sm_80+)
// ---------------------------------------------------------------------------
__device__ __forceinline__ uint32_t smem_u32(const void* p) {
    uint32_t a;
    asm("{ .reg .u64 t; cvta.to.shared.u64 t, %1; cvt.u32.u64 %0, t; }"
        : "=r"(a) : "l"(p));
    return a;
}
__device__ __forceinline__ void cpasync16(uint32_t s, const void* g) {
    asm volatile("cp.async.ca.shared.global [%0], [%1], 16;"
                 :: "r"(s), "l"(g) : "memory");
}
__device__ __forceinline__ void ldm_x4(uint32_t a, uint32_t r[4]) {
    asm volatile("ldmatrix.sync.aligned.m8n8.x4.shared.b16 {%0,%1,%2,%3}, [%4];"
                 : "=r"(r[0]), "=r"(r[1]), "=r"(r[2]), "=r"(r[3]) : "r"(a));
}
__device__ __forceinline__ void mma_bf16(float c[4], const uint32_t a[4],
                                         const uint32_t b[2]) {
    asm volatile("mma.sync.aligned.m16n8k16.row.col.f32.bf16.bf16.f32 "
                 "{%0,%1,%2,%3}, {%4,%5,%6,%7}, {%8,%9}, {%0,%1,%2,%3};"
                 : "+f"(c[0]), "+f"(c[1]), "+f"(c[2]), "+f"(c[3])
                 : "r"(a[0]), "r"(a[1]), "r"(a[2]), "r"(a[3]),
                   "r"(b[0]), "r"(b[1]));
}

// ---------------------------------------------------------------------------
// HMMA split-bf16 GEMM:  C[M,N] = (Ahi+Alo)[M,K] @ (Bhi+Blo)[N,K]^T + bias
// Block 128x128, 8 warps (4M x 2N), warp tile 32x64, K chunks of 32,
// cp.async double-buffered SMEM. Rows padded to 80B => conflict-free ldmatrix.
// 3 products per fragment pair: hi*hi + lo*hi + hi*lo into fp32 accumulators.
// ---------------------------------------------------------------------------
constexpr int MMA_STG  = 40960;          // 4 arrays * 128 rows * 80B
constexpr int MMA_SMEM = 2 * MMA_STG;    // double buffer

__global__ __launch_bounds__(256)
void gemm_mma(const __nv_bfloat16* __restrict__ Ahi, const __nv_bfloat16* __restrict__ Alo,
              const __nv_bfloat16* __restrict__ Bhi, const __nv_bfloat16* __restrict__ Blo,
              const float* __restrict__ bias, float* __restrict__ C,
              int K, int ldc, int relu)
{
    extern __shared__ char dynsmem[];
    const uint32_t sbase = smem_u32(dynsmem);
    const int tid  = threadIdx.x;
    const int lane = tid & 31;
    const int warp = tid >> 5;
    const int wm = warp & 3;      // M group (32 rows)
    const int wn = warp >> 2;     // N group (64 cols)
    const int m0 = blockIdx.y * 128;
    const int n0 = blockIdx.x * 128;

    float acc[2][8][4];
#pragma unroll
    for (int mt = 0; mt < 2; ++mt)
#pragma unroll
        for (int nt = 0; nt < 8; ++nt)
#pragma unroll
            for (int r = 0; r < 4; ++r) acc[mt][nt][r] = 0.f;

    const int nch = K >> 5;

    auto load_stage = [&](int c) {
        const int k0c = c << 5;
        const uint32_t sb = sbase + (c & 1) * MMA_STG;
#pragma unroll
        for (int i = 0; i < 2; ++i) {
            const int u = tid + i * 256;          // 0..511
            const int row = u >> 2, seg = u & 3;  // 128 rows x 4 16B-segs
            const uint32_t so = sb + row * 80 + seg * 16;
            const size_t ga = (size_t)(m0 + row) * K + k0c + seg * 8;
            const size_t gb = (size_t)(n0 + row) * K + k0c + seg * 8;
            cpasync16(so,         Ahi + ga);
            cpasync16(so + 10240, Alo + ga);
            cpasync16(so + 20480, Bhi + gb);
            cpasync16(so + 30720, Blo + gb);
        }
        asm volatile("cp.async.commit_group;" ::: "memory");
    };

    load_stage(0);

    const int lr  = lane & 7;
    const int sel = lane >> 3;
    const int a_row_off = lr + ((sel & 1) << 3);
    const int a_k_off   = (sel >> 1) << 3;
    const int b_n_off   = lr + ((sel >> 1) << 3);
    const int b_k_off   = (sel & 1) << 3;

    for (int c = 0; c < nch; ++c) {
        if (c + 1 < nch) {
            load_stage(c + 1);
            asm volatile("cp.async.wait_group 1;" ::: "memory");
        } else {
            asm volatile("cp.async.wait_group 0;" ::: "memory");
        }
        __syncthreads();
        const uint32_t sb = sbase + (c & 1) * MMA_STG;

#pragma unroll
        for (int ks = 0; ks < 2; ++ks) {
            const int kk = ks << 4;
            uint32_t ah[2][4], al[2][4], bb[8][2];
#pragma unroll
            for (int mt = 0; mt < 2; ++mt) {
                const int row = wm * 32 + mt * 16 + a_row_off;
                const uint32_t ad = sb + row * 80 + (kk + a_k_off) * 2;
                ldm_x4(ad, ah[mt]);
                ldm_x4(ad + 10240, al[mt]);
            }
#pragma unroll
            for (int p = 0; p < 4; ++p) {
                const int n = wn * 64 + p * 16 + b_n_off;
                uint32_t r[4];
                ldm_x4(sb + 20480 + n * 80 + (kk + b_k_off) * 2, r);
                bb[2 * p][0]     = r[0]; bb[2 * p][1]     = r[1];
                bb[2 * p + 1][0] = r[2]; bb[2 * p + 1][1] = r[3];
            }
#pragma unroll
            for (int mt = 0; mt < 2; ++mt)
#pragma unroll
                for (int nt = 0; nt < 8; ++nt)
                    mma_bf16(acc[mt][nt], ah[mt], bb[nt]);
#pragma unroll
            for (int mt = 0; mt < 2; ++mt)
#pragma unroll
                for (int nt = 0; nt < 8; ++nt)
                    mma_bf16(acc[mt][nt], al[mt], bb[nt]);
            // reload B as lo and do hi*lo
#pragma unroll
            for (int p = 0; p < 4; ++p) {
                const int n = wn * 64 + p * 16 + b_n_off;
                uint32_t r[4];
                ldm_x4(sb + 30720 + n * 80 + (kk + b_k_off) * 2, r);
                bb[2 * p][0]     = r[0]; bb[2 * p][1]     = r[1];
                bb[2 * p + 1][0] = r[2]; bb[2 * p + 1][1] = r[3];
            }
#pragma unroll
            for (int mt = 0; mt < 2; ++mt)
#pragma unroll
                for (int nt = 0; nt < 8; ++nt)
                    mma_bf16(acc[mt][nt], ah[mt], bb[nt]);
        }
        __syncthreads();
    }

    // epilogue
    const int rbase = m0 + wm * 32 + (lane >> 2);
    const int cbase = n0 + wn * 64 + 2 * (lane & 3);
#pragma unroll
    for (int mt = 0; mt < 2; ++mt) {
#pragma unroll
        for (int nt = 0; nt < 8; ++nt) {
            const int col = cbase + nt * 8;
            float b0v = 0.f, b1v = 0.f;
            if (bias) { b0v = bias[col]; b1v = bias[col + 1]; }
            float v0 = acc[mt][nt][0] + b0v;
            float v1 = acc[mt][nt][1] + b1v;
            float v2 = acc[mt][nt][2] + b0v;
            float v3 = acc[mt][nt][3] + b1v;
            if (relu) {
                v0 = fmaxf(v0, 0.f); v1 = fmaxf(v1, 0.f);
                v2 = fmaxf(v2, 0.f); v3 = fmaxf(v3, 0.f);
            }
            const int r0 = rbase + mt * 16;
            *(float2*)&C[(size_t)r0 * ldc + col]       = make_float2(v0, v1);
            *(float2*)&C[(size_t)(r0 + 8) * ldc + col] = make_float2(v2, v3);
        }
    }
}

// ---------------------------------------------------------------------------
// Weight transpose + bf16 hi/lo split: W[l][K][N] -> hi/lo [l][N][K]
// ---------------------------------------------------------------------------
__global__ void conv_w(const float* __restrict__ W, __nv_bfloat16* __restrict__ hi,
                       __nv_bfloat16* __restrict__ lo, int K, int N)
{
    __shared__ float t[32][33];
    const int l = blockIdx.z;
    W  += (size_t)l * K * N;
    hi += (size_t)l * K * N;
    lo += (size_t)l * K * N;
    const int k0 = blockIdx.y * 32, n0 = blockIdx.x * 32;
    const int tx = threadIdx.x, ty = threadIdx.y;   // 32 x 8
#pragma unroll
    for (int i = ty; i < 32; i += 8)
        t[i][tx] = W[(size_t)(k0 + i) * N + n0 + tx];
    __syncthreads();
#pragma unroll
    for (int i = ty; i < 32; i += 8) {
        const float v = t[tx][i];                       // W[k0+tx][n0+i]
        const __nv_bfloat16 h = __float2bfloat16(v);
        const __nv_bfloat16 r = __float2bfloat16(v - __bfloat162float(h));
        hi[(size_t)(n0 + i) * K + k0 + tx] = h;
        lo[(size_t)(n0 + i) * K + k0 + tx] = r;
    }
}

// ---------------------------------------------------------------------------
// Activation bf16 hi/lo split (elementwise, float4)
// ---------------------------------------------------------------------------
__global__ void split_act(const float* __restrict__ x, __nv_bfloat16* __restrict__ hi,
                          __nv_bfloat16* __restrict__ lo, int n4)
{
    const int i = blockIdx.x * 256 + threadIdx.x;
    if (i >= n4) return;
    const float4 v = ((const float4*)x)[i];
    const float f[4] = {v.x, v.y, v.z, v.w};
    unsigned short hh[4], ll[4];
#pragma unroll
    for (int j = 0; j < 4; j++) {
        const __nv_bfloat16 hb = __float2bfloat16(f[j]);
        const __nv_bfloat16 lb = __float2bfloat16(f[j] - __bfloat162float(hb));
        hh[j] = __bfloat16_as_ushort(hb);
        ll[j] = __bfloat16_as_ushort(lb);
    }
    ((uint2*)hi)[i] = *(const uint2*)hh;
    ((uint2*)lo)[i] = *(const uint2*)ll;
}

// ---------------------------------------------------------------------------
// Precompute sinusoid rate[d]
// ---------------------------------------------------------------------------
__global__ void rate_kernel(float* __restrict__ rate)
{
    const int d = blockIdx.x * 256 + threadIdx.x;
    if (d >= DD) return;
    const double LN1E4 = 9.210340371976184;
    const int par = d & 1;
    const float r1 = (float)exp(-LN1E4 * (double)d   / 1024.0);
    const float r2 = (float)exp( LN1E4 * (double)par / 1024.0);
    rate[d] = r1 * r2;
}

__global__ void embed_kernel(const int* __restrict__ x,
                             const float* __restrict__ emb,
                             const float* __restrict__ rate,
                             float* __restrict__ h)
{
    const int bs = blockIdx.x;
    const int s  = bs & (SS - 1);
    const int tok = x[bs];
    const float* e = emb + (size_t)tok * DD;
    float* hp = h + (size_t)bs * DD;
    for (int d = threadIdx.x; d < DD; d += blockDim.x) {
        const int par = d & 1;
        const float ph = (float)s * rate[d] + 1.5707964f * (float)par;
        hp[d] = e[d] * 32.0f + sinf(ph);
    }
}

// ---------------------------------------------------------------------------
// 128x128x8 fp32 SIMT GEMM (attention QE/QK only)
// ---------------------------------------------------------------------------
template<bool TRANSB, bool RELU, int SKIP>
__global__ __launch_bounds__(256, 2)
void gemm128(const float* __restrict__ A, const float* __restrict__ Bm,
             const float* __restrict__ bias, float* __restrict__ C,
             int K, int lda, int ldb, int ldc, int zdiv,
             long long sA1, long long sA2,
             long long sB1, long long sB2,
             long long sC1, long long sC2)
{
    const int m0 = blockIdx.y * 128;
    const int n0 = blockIdx.x * 128;
    if (SKIP == 1 && (m0 + n0 + 254 < SS - 1)) return;
    if (SKIP == 2 && (n0 >= m0 + 128)) return;

    __shared__ __align__(16) float As[8][128];
    __shared__ __align__(16) float Bs[8][128];

    const int tid = threadIdx.x;
    const int tx = tid & 15;
    const int ty = tid >> 4;

    const int z  = blockIdx.z;
    const int zb = z / zdiv;
    const int zh = z % zdiv;
    A  += (size_t)zb * sA1 + (size_t)zh * sA2;
    Bm += (size_t)zb * sB1 + (size_t)zh * sB2;
    C  += (size_t)zb * sC1 + (size_t)zh * sC2;

    const int arow = tid >> 1;
    const int acol = (tid & 1) * 4;
    const int brow = tid >> 5;
    const int bcol = (tid & 31) * 4;
    const int tbn  = tid >> 1;
    const int tbk  = (tid & 1) * 4;

    float acc[8][8];
#pragma unroll
    for (int i = 0; i < 8; i++)
#pragma unroll
        for (int j = 0; j < 8; j++) acc[i][j] = 0.f;

    const float* Ap = A + (size_t)(m0 + arow) * lda + acol;

    float4 pa, pb;
    pa = *(const float4*)&Ap[0];
    if (!TRANSB) pb = *(const float4*)&Bm[(size_t)brow * ldb + n0 + bcol];
    else         pb = *(const float4*)&Bm[(size_t)(n0 + tbn) * ldb + tbk];

    for (int k0 = 0; k0 < K; k0 += 8) {
        As[acol + 0][arow] = pa.x;
        As[acol + 1][arow] = pa.y;
        As[acol + 2][arow] = pa.z;
        As[acol + 3][arow] = pa.w;
        if (!TRANSB) {
            *(float4*)&Bs[brow][bcol] = pb;
        } else {
            Bs[tbk + 0][tbn] = pb.x;
            Bs[tbk + 1][tbn] = pb.y;
            Bs[tbk + 2][tbn] = pb.z;
            Bs[tbk + 3][tbn] = pb.w;
        }
        __syncthreads();

        if (k0 + 8 < K) {
            pa = *(const float4*)&Ap[k0 + 8];
            if (!TRANSB) pb = *(const float4*)&Bm[(size_t)(k0 + 8 + brow) * ldb + n0 + bcol];
            else         pb = *(const float4*)&Bm[(size_t)(n0 + tbn) * ldb + k0 + 8 + tbk];
        }

#pragma unroll
        for (int kk = 0; kk < 8; kk++) {
            const float4 a0 = *(const float4*)&As[kk][ty * 4];
            const float4 a1 = *(const float4*)&As[kk][64 + ty * 4];
            const float4 b0 = *(const float4*)&Bs[kk][tx * 4];
            const float4 b1 = *(const float4*)&Bs[kk][64 + tx * 4];
            const float ar[8] = {a0.x, a0.y, a0.z, a0.w, a1.x, a1.y, a1.z, a1.w};
            const float br[8] = {b0.x, b0.y, b0.z, b0.w, b1.x, b1.y, b1.z, b1.w};
#pragma unroll
            for (int i = 0; i < 8; i++)
#pragma unroll
                for (int j = 0; j < 8; j++)
                    acc[i][j] += ar[i] * br[j];
        }
        __syncthreads();
    }

    float bv[8] = {0, 0, 0, 0, 0, 0, 0, 0};
    if (bias) {
#pragma unroll
        for (int j = 0; j < 4; j++) {
            bv[j]     = bias[n0 + tx * 4 + j];
            bv[4 + j] = bias[n0 + 64 + tx * 4 + j];
        }
    }
#pragma unroll
    for (int rq = 0; rq < 2; rq++) {
#pragma unroll
        for (int i = 0; i < 4; i++) {
            const int r = m0 + rq * 64 + ty * 4 + i;
            float4 o0, o1;
            o0.x = acc[rq * 4 + i][0] + bv[0];
            o0.y = acc[rq * 4 + i][1] + bv[1];
            o0.z = acc[rq * 4 + i][2] + bv[2];
            o0.w = acc[rq * 4 + i][3] + bv[3];
            o1.x = acc[rq * 4 + i][4] + bv[4];
            o1.y = acc[rq * 4 + i][5] + bv[5];
            o1.z = acc[rq * 4 + i][6] + bv[6];
            o1.w = acc[rq * 4 + i][7] + bv[7];
            if (RELU) {
                o0.x = fmaxf(o0.x, 0.f); o0.y = fmaxf(o0.y, 0.f);
                o0.z = fmaxf(o0.z, 0.f); o0.w = fmaxf(o0.w, 0.f);
                o1.x = fmaxf(o1.x, 0.f); o1.y = fmaxf(o1.y, 0.f);
                o1.z = fmaxf(o1.z, 0.f); o1.w = fmaxf(o1.w, 0.f);
            }
            *(float4*)&C[(size_t)r * ldc + n0 + tx * 4]      = o0;
            *(float4*)&C[(size_t)r * ldc + n0 + 64 + tx * 4] = o1;
        }
    }
}

// ---------------------------------------------------------------------------
// 64x64x16 fp32 GEMM (AV), K capped to causal region
// ---------------------------------------------------------------------------
#define BSWZ(k, n) ((n) ^ (((k) & 15) << 2))

template<bool RELU, bool KCAP>
__global__ __launch_bounds__(256)
void gemm64(const float* __restrict__ A, const float* __restrict__ Bm,
            const float* __restrict__ bias, float* __restrict__ C,
            int K, int lda, int ldb, int ldc, int zdiv,
            long long sA1, long long sA2,
            long long sB1, long long sB2,
            long long sC1, long long sC2)
{
    __shared__ float As[64][17];
    __shared__ __align__(16) float Bs[16][64];

    const int tid = threadIdx.x;
    const int tx = tid & 15;
    const int ty = tid >> 4;
    const int m0 = blockIdx.y * 64;
    const int n0 = blockIdx.x * 64;

    const int z  = blockIdx.z;
    const int zb = z / zdiv;
    const int zh = z % zdiv;
    A  += (size_t)zb * sA1 + (size_t)zh * sA2;
    Bm += (size_t)zb * sB1 + (size_t)zh * sB2;
    C  += (size_t)zb * sC1 + (size_t)zh * sC2;

    float acc[4][4];
#pragma unroll
    for (int i = 0; i < 4; i++)
#pragma unroll
        for (int j = 0; j < 4; j++) acc[i][j] = 0.f;

    const int ac = tid & 15;
    const int ar = tid >> 4;
    const int bn = tid & 63;
    const int bk = tid >> 6;

    const int Keff = KCAP ? min(K, m0 + 64) : K;

    for (int k0 = 0; k0 < Keff; k0 += 16) {
#pragma unroll
        for (int i = 0; i < 4; i++) {
            const int m = ar + i * 16;
            As[m][ac] = A[(size_t)(m0 + m) * lda + (k0 + ac)];
        }
#pragma unroll
        for (int i = 0; i < 4; i++) {
            const int kk = bk + i * 4;
            Bs[kk][BSWZ(kk, bn)] = Bm[(size_t)(k0 + kk) * ldb + (n0 + bn)];
        }
        __syncthreads();
#pragma unroll
        for (int kk = 0; kk < 16; kk++) {
            const float4 bvv = *(const float4*)&Bs[kk][BSWZ(kk, tx * 4)];
            const float a0 = As[ty * 4 + 0][kk];
            const float a1 = As[ty * 4 + 1][kk];
            const float a2 = As[ty * 4 + 2][kk];
            const float a3 = As[ty * 4 + 3][kk];
            acc[0][0] += a0 * bvv.x; acc[0][1] += a0 * bvv.y;
            acc[0][2] += a0 * bvv.z; acc[0][3] += a0 * bvv.w;
            acc[1][0] += a1 * bvv.x; acc[1][1] += a1 * bvv.y;
            acc[1][2] += a1 * bvv.z; acc[1][3] += a1 * bvv.w;
            acc[2][0] += a2 * bvv.x; acc[2][1] += a2 * bvv.y;
            acc[2][2] += a2 * bvv.z; acc[2][3] += a2 * bvv.w;
            acc[3][0] += a3 * bvv.x; acc[3][1] += a3 * bvv.y;
            acc[3][2] += a3 * bvv.z; acc[3][3] += a3 * bvv.w;
        }
        __syncthreads();
    }

    float bvals[4] = {0.f, 0.f, 0.f, 0.f};
    if (bias) {
#pragma unroll
        for (int j = 0; j < 4; j++) bvals[j] = bias[n0 + tx * 4 + j];
    }
#pragma unroll
    for (int i = 0; i < 4; i++) {
#pragma unroll
        for (int j = 0; j < 4; j++) {
            float vo = acc[i][j] + bvals[j];
            if (RELU) vo = fmaxf(vo, 0.f);
            C[(size_t)(m0 + ty * 4 + i) * ldc + (n0 + tx * 4 + j)] = vo;
        }
    }
}

// ---------------------------------------------------------------------------
// Fused Srel gather + scale + causal/pad mask + softmax, causal-truncated.
// ---------------------------------------------------------------------------
__global__ __launch_bounds__(256)
void attn_softmax(float* __restrict__ lg, const float* __restrict__ qe,
                  const int* __restrict__ x)
{
    const int i  = blockIdx.x;
    const int bh = blockIdx.y;
    const int b  = bh >> 4;
    float* row        = lg + (size_t)bh * SS * SS + (size_t)i * SS;
    const float* qrow = qe + (size_t)bh * SS * SS + (size_t)i * SS;
    const int* xb = x + b * SS;
    const int t = threadIdx.x;
    const int nch = (i >> 8) + 1;

    float vals[4];
    float mx = -1e30f;
    for (int c = 0; c < nch; c++) {
        const int j = c * 256 + t;
        float vv = -1e30f;
        if (j <= i) {
            vv = (row[j] + qrow[SS - 1 - i + j]) * ATT_SCALE;
            if (xb[j] == 0) vv -= 1e9f;
        }
        vals[c] = vv;
        mx = fmaxf(mx, vv);
    }
    __shared__ float sh[8];
#pragma unroll
    for (int o = 16; o > 0; o >>= 1) mx = fmaxf(mx, __shfl_xor_sync(0xffffffffu, mx, o));
    if ((t & 31) == 0) sh[t >> 5] = mx;
    __syncthreads();
    mx = sh[0];
#pragma unroll
    for (int w = 1; w < 8; w++) mx = fmaxf(mx, sh[w]);

    float s = 0.f;
    for (int c = 0; c < nch; c++) { vals[c] = expf(vals[c] - mx); s += vals[c]; }
#pragma unroll
    for (int o = 16; o > 0; o >>= 1) s += __shfl_xor_sync(0xffffffffu, s, o);
    __syncthreads();
    if ((t & 31) == 0) sh[t >> 5] = s;
    __syncthreads();
    s = 0.f;
#pragma unroll
    for (int w = 0; w < 8; w++) s += sh[w];
    const float inv = 1.f / s;
    for (int c = 0; c < nch; c++) row[c * 256 + t] = vals[c] * inv;
}

// ---------------------------------------------------------------------------
// LayerNorm over last dim (1024), in place.
// ---------------------------------------------------------------------------
__global__ __launch_bounds__(256)
void ln_kernel(float* __restrict__ xio, const float* __restrict__ g,
               const float* __restrict__ be)
{
    const int row = blockIdx.x;
    float* p = xio + (size_t)row * DD;
    const int t = threadIdx.x;
    float v[4];
    float s = 0.f, s2 = 0.f;
#pragma unroll
    for (int c = 0; c < 4; c++) {
        v[c] = p[t + c * 256];
        s += v[c];
        s2 += v[c] * v[c];
    }
    __shared__ float sh1[8], sh2[8];
#pragma unroll
    for (int o = 16; o > 0; o >>= 1) {
        s  += __shfl_xor_sync(0xffffffffu, s,  o);
        s2 += __shfl_xor_sync(0xffffffffu, s2, o);
    }
    if ((t & 31) == 0) { sh1[t >> 5] = s; sh2[t >> 5] = s2; }
    __syncthreads();
    s = 0.f; s2 = 0.f;
#pragma unroll
    for (int w = 0; w < 8; w++) { s += sh1[w]; s2 += sh2[w]; }
    const float mu  = s  * (1.f / DD);
    const float var = s2 * (1.f / DD) - mu * mu;
    const float inv = rsqrtf(var + 1e-6f);
#pragma unroll
    for (int c = 0; c < 4; c++) {
        const int d = t + c * 256;
        p[d] = (v[c] - mu) * inv * g[d] + be[d];
    }
}

// ---------------------------------------------------------------------------
// Host side
// ---------------------------------------------------------------------------
template<bool TRANSB, bool RELU, int SKIP>
static void run_g128(const float* A, const float* Bm, const float* bias, float* C,
                     int M, int N, int K, int lda, int ldb, int ldc,
                     int batch, int zdiv,
                     long long sA1, long long sA2,
                     long long sB1, long long sB2,
                     long long sC1, long long sC2)
{
    dim3 grid(N / 128, M / 128, batch);
    gemm128<TRANSB, RELU, SKIP><<<grid, 256>>>(A, Bm, bias, C, K, lda, ldb, ldc,
                                               zdiv, sA1, sA2, sB1, sB2, sC1, sC2);
}

static void run_mma(const __nv_bfloat16* ahi, const __nv_bfloat16* alo,
                    const __nv_bfloat16* bhi, const __nv_bfloat16* blo,
                    const float* bias, float* C, int M, int N, int K, int relu)
{
    dim3 grid(N / 128, M / 128);
    gemm_mma<<<grid, 256, MMA_SMEM>>>(ahi, alo, bhi, blo, bias, C, K, N, relu);
}

extern "C" void kernel_launch(void* const* d_in, const int* in_sizes, int n_in,
                              void* d_out, int out_size)
{
    const int*   x   = (const int*)  d_in[0];
    const float* emb = (const float*)d_in[1];
    const float* Wq  = (const float*)d_in[2];
    const float* bq  = (const float*)d_in[3];
    const float* Wk  = (const float*)d_in[4];
    const float* bk  = (const float*)d_in[5];
    const float* Wv  = (const float*)d_in[6];
    const float* bv  = (const float*)d_in[7];
    const float* Wo  = (const float*)d_in[8];
    const float* bo  = (const float*)d_in[9];
    const float* W1  = (const float*)d_in[10];
    const float* b1  = (const float*)d_in[11];
    const float* W2  = (const float*)d_in[12];
    const float* b2  = (const float*)d_in[13];
    const float* g1  = (const float*)d_in[14];
    const float* be1 = (const float*)d_in[15];
    const float* g2  = (const float*)d_in[16];
    const float* be2 = (const float*)d_in[17];
    const float* E   = (const float*)d_in[18];
    const float* Wf  = (const float*)d_in[19];
    const float* bf  = (const float*)d_in[20];
    float* out = (float*)d_out;

    cudaFuncSetAttribute(gemm_mma, cudaFuncAttributeMaxDynamicSharedMemorySize,
                         MMA_SMEM);

    float *h, *q, *k, *v, *at, *t1, *ff, *qe, *lg, *rate;
    cudaGetSymbolAddress((void**)&h,  g_h);
    cudaGetSymbolAddress((void**)&q,  g_q);
    cudaGetSymbolAddress((void**)&k,  g_k);
    cudaGetSymbolAddress((void**)&v,  g_v);
    cudaGetSymbolAddress((void**)&at, g_attn);
    cudaGetSymbolAddress((void**)&t1, g_t1);
    cudaGetSymbolAddress((void**)&ff, g_ff);
    cudaGetSymbolAddress((void**)&qe, g_qe);
    cudaGetSymbolAddress((void**)&lg, g_lg);
    cudaGetSymbolAddress((void**)&rate, g_rate);

    __nv_bfloat16 *wqh, *wql, *wkh, *wkl, *wvh, *wvl, *woh, *wol;
    __nv_bfloat16 *w1h, *w1l, *w2h, *w2l, *wfh, *wfl, *ah, *al;
    cudaGetSymbolAddress((void**)&wqh, g_wq_h); cudaGetSymbolAddress((void**)&wql, g_wq_l);
    cudaGetSymbolAddress((void**)&wkh, g_wk_h); cudaGetSymbolAddress((void**)&wkl, g_wk_l);
    cudaGetSymbolAddress((void**)&wvh, g_wv_h); cudaGetSymbolAddress((void**)&wvl, g_wv_l);
    cudaGetSymbolAddress((void**)&woh, g_wo_h); cudaGetSymbolAddress((void**)&wol, g_wo_l);
    cudaGetSymbolAddress((void**)&w1h, g_w1_h); cudaGetSymbolAddress((void**)&w1l, g_w1_l);
    cudaGetSymbolAddress((void**)&w2h, g_w2_h); cudaGetSymbolAddress((void**)&w2l, g_w2_l);
    cudaGetSymbolAddress((void**)&wfh, g_wf_h); cudaGetSymbolAddress((void**)&wfl, g_wf_l);
    cudaGetSymbolAddress((void**)&ah,  g_ah);   cudaGetSymbolAddress((void**)&al,  g_al);

    const int M = BB * SS;  // 2048
    const long long sSD  = (long long)SS * DD;
    const long long sHSS = (long long)HH * SS * SS;
    const long long sSSq = (long long)SS * SS;

    // weight conversion (transpose + hi/lo split)
    {
        dim3 tb(32, 8);
        conv_w<<<dim3(DD / 32, DD / 32, LL), tb>>>(Wq, wqh, wql, DD, DD);
        conv_w<<<dim3(DD / 32, DD / 32, LL), tb>>>(Wk, wkh, wkl, DD, DD);
        conv_w<<<dim3(DD / 32, DD / 32, LL), tb>>>(Wv, wvh, wvl, DD, DD);
        conv_w<<<dim3(DD / 32, DD / 32, LL), tb>>>(Wo, woh, wol, DD, DD);
        conv_w<<<dim3(DF / 32, DD / 32, LL), tb>>>(W1, w1h, w1l, DD, DF);
        conv_w<<<dim3(DD / 32, DF / 32, LL), tb>>>(W2, w2h, w2l, DF, DD);
        conv_w<<<dim3(VV / 32, DD / 32, 1),  tb>>>(Wf, wfh, wfl, DD, VV);
    }

    rate_kernel<<<4, 256>>>(rate);
    embed_kernel<<<BB * SS, 256>>>(x, emb, rate, h);

    for (int l = 0; l < LL; l++) {
        const size_t wdd = (size_t)l * DD * DD;
        const size_t wdf = (size_t)l * DF * DD;

        // split h -> bf16 hi/lo, then QKV projections on tensor cores
        split_act<<<(M * DD / 4 + 255) / 256, 256>>>(h, ah, al, M * DD / 4);
        run_mma(ah, al, wqh + wdd, wql + wdd, bq + l * DD, q, M, DD, DD, 0);
        run_mma(ah, al, wkh + wdd, wkl + wdd, bk + l * DD, k, M, DD, DD, 0);
        run_mma(ah, al, wvh + wdd, wvl + wdd, bv + l * DD, v, M, DD, DD, 0);

        const float* El = E + (size_t)l * SS * HD;
        // QE (lower-left tiles skipped)
        run_g128<true, false, 1>(q, El, nullptr, qe, SS, SS, HD, DD, HD, SS,
                                 BB * HH, HH, sSD, HD, 0, 0, sHSS, sSSq);
        // QK^T (strictly-upper tiles skipped)
        run_g128<true, false, 2>(q, k, nullptr, lg, SS, SS, HD, DD, DD, SS,
                                 BB * HH, HH, sSD, HD, sSD, HD, sHSS, sSSq);

        attn_softmax<<<dim3(SS, BB * HH), 256>>>(lg, qe, x);

        // attn = aw @ v, K capped at causal boundary
        {
            dim3 grid(HD / 64, SS / 64, BB * HH);
            gemm64<false, true><<<grid, 256>>>(lg, v, nullptr, at, SS, SS, DD, DD,
                                               HH, sHSS, sSSq, sSD, HD, sSD, HD);
        }

        // Wo projection + LN1 (tensor cores)
        split_act<<<(M * DD / 4 + 255) / 256, 256>>>(at, ah, al, M * DD / 4);
        run_mma(ah, al, woh + wdd, wol + wdd, bo + l * DD, t1, M, DD, DD, 0);
        ln_kernel<<<BB * SS, 256>>>(t1, g1 + l * DD, be1 + l * DD);

        // FFN on tensor cores
        split_act<<<(M * DD / 4 + 255) / 256, 256>>>(t1, ah, al, M * DD / 4);
        run_mma(ah, al, w1h + wdf, w1l + wdf, b1 + l * DF, ff, M, DF, DD, 1);
        split_act<<<(M * DF / 4 + 255) / 256, 256>>>(ff, ah, al, M * DF / 4);
        run_mma(ah, al, w2h + wdf, w2l + wdf, b2 + l * DD, h, M, DD, DF, 0);
        ln_kernel<<<BB * SS, 256>>>(h, g2 + l * DD, be2 + l * DD);
    }

    // final projection to vocab (tensor cores)
    split_act<<<(M * DD / 4 + 255) / 256, 256>>>(h, ah, al, M * DD / 4);
    run_mma(ah, al, wfh, wfl, bf, out, M, VV, DD, 0);
}

// round 5
// speedup vs baseline: 3.1430x; 1.2008x over previous
#include <cuda_runtime.h>
#include <cuda_bf16.h>
#include <math.h>
#include <stdint.h>

// ---------------------------------------------------------------------------
// Problem constants
// ---------------------------------------------------------------------------
constexpr int BB = 2;     // batch
constexpr int SS = 1024;  // seq len
constexpr int DD = 1024;  // model dim
constexpr int HH = 16;    // heads
constexpr int LL = 6;     // layers
constexpr int VV = 256;   // vocab
constexpr int HD = 64;    // head dim
constexpr int DF = 512;   // ffn dim
constexpr float ATT_SCALE = 0.125f;  // 1/sqrt(64)

// ---------------------------------------------------------------------------
// Scratch (static device globals -- no allocations allowed)
// ---------------------------------------------------------------------------
__device__ float g_t1 [BB * SS * DD];                 // pre-LN fp32
__device__ float g_h2 [BB * SS * DD];                 // pre-LN fp32
__device__ float g_qe [(size_t)BB * HH * SS * SS];    // 134 MB
__device__ float g_lg [(size_t)BB * HH * SS * SS];    // 134 MB
__device__ float g_rate[DD];

// split activation buffers
__device__ __nv_bfloat16 g_xh [BB * SS * DD], g_xl [BB * SS * DD];  // layer in
__device__ __nv_bfloat16 g_qh [BB * SS * DD], g_ql [BB * SS * DD];
__device__ __nv_bfloat16 g_kh [BB * SS * DD], g_kl [BB * SS * DD];
__device__ __nv_bfloat16 g_vth[BB * DD * SS], g_vtl[BB * DD * SS];  // v^T per head
__device__ __nv_bfloat16 g_ath[BB * SS * DD], g_atl[BB * SS * DD];  // attn out
__device__ __nv_bfloat16 g_ffh[BB * SS * DF], g_ffl[BB * SS * DF];
__device__ __nv_bfloat16 g_awh[(size_t)BB * HH * SS * SS];          // 67 MB
__device__ __nv_bfloat16 g_awl[(size_t)BB * HH * SS * SS];          // 67 MB
__device__ __nv_bfloat16 g_eh [LL * SS * HD], g_el [LL * SS * HD];

// bf16 split weight buffers ([N, K] transposed, hi/lo)
__device__ __nv_bfloat16 g_wq_h[LL * DD * DD], g_wq_l[LL * DD * DD];
__device__ __nv_bfloat16 g_wk_h[LL * DD * DD], g_wk_l[LL * DD * DD];
__device__ __nv_bfloat16 g_wv_h[LL * DD * DD], g_wv_l[LL * DD * DD];
__device__ __nv_bfloat16 g_wo_h[LL * DD * DD], g_wo_l[LL * DD * DD];
__device__ __nv_bfloat16 g_w1_h[LL * DF * DD], g_w1_l[LL * DF * DD];
__device__ __nv_bfloat16 g_w2_h[LL * DD * DF], g_w2_l[LL * DD * DF];
__device__ __nv_bfloat16 g_wf_h[VV * DD],      g_wf_l[VV * DD];

// ---------------------------------------------------------------------------
// PTX helpers (mma.sync / ldmatrix / cp.async -- standard ISA, sm_80+)
// ---------------------------------------------------------------------------
__device__ __forceinline__ uint32_t smem_u32(const void* p) {
    uint32_t a;
    asm("{ .reg .u64 t; cvta.to.shared.u64 t, %1; cvt.u32.u64 %0, t; }"
        : "=r"(a) : "l"(p));
    return a;
}
__device__ __forceinline__ void cpasync16(uint32_t s, const void* g) {
    asm volatile("cp.async.ca.shared.global [%0], [%1], 16;"
                 :: "r"(s), "l"(g) : "memory");
}
__device__ __forceinline__ void ldm_x4(uint32_t a, uint32_t r[4]) {
    asm volatile("ldmatrix.sync.aligned.m8n8.x4.shared.b16 {%0,%1,%2,%3}, [%4];"
                 : "=r"(r[0]), "=r"(r[1]), "=r"(r[2]), "=r"(r[3]) : "r"(a));
}
__device__ __forceinline__ void mma_bf16(float c[4], const uint32_t a[4],
                                         const uint32_t b[2]) {
    asm volatile("mma.sync.aligned.m16n8k16.row.col.f32.bf16.bf16.f32 "
                 "{%0,%1,%2,%3}, {%4,%5,%6,%7}, {%8,%9}, {%0,%1,%2,%3};"
                 : "+f"(c[0]), "+f"(c[1]), "+f"(c[2]), "+f"(c[3])
                 : "r"(a[0]), "r"(a[1]), "r"(a[2]), "r"(a[3]),
                   "r"(b[0]), "r"(b[1]));
}
__device__ __forceinline__ uint32_t pack_bf2(float a, float b) {
    __nv_bfloat162 t = __floats2bfloat162_rn(a, b);
    return *(uint32_t*)&t;
}

// ---------------------------------------------------------------------------
// Unified batched split-bf16 HMMA GEMM:
//   C[M,N] = (Ahi+Alo)[M,K] @ (Bhi+Blo)[N,K]^T + bias
// BM=128 fixed, BN 128 or 64; 8 warps (4M x 2N), warp tile 32 x BN/2.
// SKIP: 0 none, 1 QE anti-diagonal skip, 2 causal strictly-upper skip.
// KCAP: cap K loop at m0+128 (causal AV).
// OUT:  0 = fp32 C;  1 = split bf16 (Ch,Cl);  2 = split bf16 TRANSPOSED.
// Batched via blockIdx.z -> (zb=z/zdiv, zh=z%zdiv), pointer strides.
// ---------------------------------------------------------------------------
template<int BN, int SKIP, bool KCAP, int OUT, bool RELU>
__global__ __launch_bounds__(256)
void gemm_mma(const __nv_bfloat16* __restrict__ Ahi, const __nv_bfloat16* __restrict__ Alo,
              const __nv_bfloat16* __restrict__ Bhi, const __nv_bfloat16* __restrict__ Blo,
              const float* __restrict__ bias, float* __restrict__ C,
              __nv_bfloat16* __restrict__ Ch, __nv_bfloat16* __restrict__ Cl,
              int K, int lda, int ldb, int ldc, int zdiv,
              long long sA1, long long sA2,
              long long sB1, long long sB2,
              long long sC1, long long sC2)
{
    constexpr int ABY = 10240;            // 128 rows * 80B
    constexpr int BBY = BN * 80;
    constexpr int STG = 2 * ABY + 2 * BBY;
    constexpr int NT  = BN / 16;          // n8-tiles per warp
    constexpr int BN2 = BN / 2;

    const int m0 = blockIdx.y * 128;
    const int n0 = blockIdx.x * BN;
    if (SKIP == 1 && (m0 + n0 + 127 + BN - 1 < SS - 1)) return;
    if (SKIP == 2 && (n0 >= m0 + 128)) return;

    extern __shared__ char dynsmem[];
    const uint32_t sbase = smem_u32(dynsmem);
    const int tid  = threadIdx.x;
    const int lane = tid & 31;
    const int warp = tid >> 5;
    const int wm = warp & 3;
    const int wn = warp >> 2;

    const int z  = blockIdx.z;
    const int zb = z / zdiv;
    const int zh = z % zdiv;
    Ahi += (size_t)zb * sA1 + (size_t)zh * sA2;
    Alo += (size_t)zb * sA1 + (size_t)zh * sA2;
    Bhi += (size_t)zb * sB1 + (size_t)zh * sB2;
    Blo += (size_t)zb * sB1 + (size_t)zh * sB2;
    if (OUT == 0) C  += (size_t)zb * sC1 + (size_t)zh * sC2;
    else { Ch += (size_t)zb * sC1 + (size_t)zh * sC2;
           Cl += (size_t)zb * sC1 + (size_t)zh * sC2; }

    float acc[2][NT][4];
#pragma unroll
    for (int mt = 0; mt < 2; ++mt)
#pragma unroll
        for (int nt = 0; nt < NT; ++nt)
#pragma unroll
            for (int r = 0; r < 4; ++r) acc[mt][nt][r] = 0.f;

    const int Keff = KCAP ? min(K, m0 + 128) : K;
    const int nch  = Keff >> 5;

    auto load_stage = [&](int c) {
        const int k0c = c << 5;
        const uint32_t sb = sbase + (c & 1) * STG;
#pragma unroll
        for (int i = 0; i < 2; ++i) {                 // A: 512 units
            const int u = tid + i * 256;
            const int row = u >> 2, seg = u & 3;
            const uint32_t so = sb + row * 80 + seg * 16;
            const size_t ga = (size_t)(m0 + row) * lda + k0c + seg * 8;
            cpasync16(so,       Ahi + ga);
            cpasync16(so + ABY, Alo + ga);
        }
        constexpr int BU = (BN * 4) / 256;            // 2 or 1
#pragma unroll
        for (int i = 0; i < BU; ++i) {
            const int u = tid + i * 256;
            const int row = u >> 2, seg = u & 3;
            const uint32_t so = sb + 2 * ABY + row * 80 + seg * 16;
            const size_t gb = (size_t)(n0 + row) * ldb + k0c + seg * 8;
            cpasync16(so,       Bhi + gb);
            cpasync16(so + BBY, Blo + gb);
        }
        asm volatile("cp.async.commit_group;" ::: "memory");
    };

    load_stage(0);

    const int lr  = lane & 7;
    const int sel = lane >> 3;
    const int a_row_off = lr + ((sel & 1) << 3);
    const int a_k_off   = (sel >> 1) << 3;
    const int b_n_off   = lr + ((sel >> 1) << 3);
    const int b_k_off   = (sel & 1) << 3;

    for (int c = 0; c < nch; ++c) {
        if (c + 1 < nch) {
            load_stage(c + 1);
            asm volatile("cp.async.wait_group 1;" ::: "memory");
        } else {
            asm volatile("cp.async.wait_group 0;" ::: "memory");
        }
        __syncthreads();
        const uint32_t sb = sbase + (c & 1) * STG;

#pragma unroll
        for (int ks = 0; ks < 2; ++ks) {
            const int kk = ks << 4;
            uint32_t ah[2][4], al[2][4], bb[NT][2];
#pragma unroll
            for (int mt = 0; mt < 2; ++mt) {
                const int row = wm * 32 + mt * 16 + a_row_off;
                const uint32_t ad = sb + row * 80 + (kk + a_k_off) * 2;
                ldm_x4(ad, ah[mt]);
                ldm_x4(ad + ABY, al[mt]);
            }
#pragma unroll
            for (int p = 0; p < NT / 2; ++p) {
                const int n = wn * BN2 + p * 16 + b_n_off;
                uint32_t r[4];
                ldm_x4(sb + 2 * ABY + n * 80 + (kk + b_k_off) * 2, r);
                bb[2 * p][0]     = r[0]; bb[2 * p][1]     = r[1];
                bb[2 * p + 1][0] = r[2]; bb[2 * p + 1][1] = r[3];
            }
#pragma unroll
            for (int mt = 0; mt < 2; ++mt)
#pragma unroll
                for (int nt = 0; nt < NT; ++nt)
                    mma_bf16(acc[mt][nt], ah[mt], bb[nt]);
#pragma unroll
            for (int mt = 0; mt < 2; ++mt)
#pragma unroll
                for (int nt = 0; nt < NT; ++nt)
                    mma_bf16(acc[mt][nt], al[mt], bb[nt]);
            // reload B as lo and do hi*lo
#pragma unroll
            for (int p = 0; p < NT / 2; ++p) {
                const int n = wn * BN2 + p * 16 + b_n_off;
                uint32_t r[4];
                ldm_x4(sb + 2 * ABY + BBY + n * 80 + (kk + b_k_off) * 2, r);
                bb[2 * p][0]     = r[0]; bb[2 * p][1]     = r[1];
                bb[2 * p + 1][0] = r[2]; bb[2 * p + 1][1] = r[3];
            }
#pragma unroll
            for (int mt = 0; mt < 2; ++mt)
#pragma unroll
                for (int nt = 0; nt < NT; ++nt)
                    mma_bf16(acc[mt][nt], ah[mt], bb[nt]);
        }
        __syncthreads();
    }

    // epilogue
    const int rbase = m0 + wm * 32 + (lane >> 2);
    const int cbase = n0 + wn * BN2 + 2 * (lane & 3);
#pragma unroll
    for (int mt = 0; mt < 2; ++mt) {
#pragma unroll
        for (int nt = 0; nt < NT; ++nt) {
            const int col = cbase + nt * 8;
            float b0v = 0.f, b1v = 0.f;
            if (bias) { b0v = bias[col]; b1v = bias[col + 1]; }
            float v0 = acc[mt][nt][0] + b0v;
            float v1 = acc[mt][nt][1] + b1v;
            float v2 = acc[mt][nt][2] + b0v;
            float v3 = acc[mt][nt][3] + b1v;
            if (RELU) {
                v0 = fmaxf(v0, 0.f); v1 = fmaxf(v1, 0.f);
                v2 = fmaxf(v2, 0.f); v3 = fmaxf(v3, 0.f);
            }
            const int r0 = rbase + mt * 16;
            if (OUT == 0) {
                *(float2*)&C[(size_t)r0 * ldc + col]       = make_float2(v0, v1);
                *(float2*)&C[(size_t)(r0 + 8) * ldc + col] = make_float2(v2, v3);
            } else if (OUT == 1) {
                const float h0 = __bfloat162float(__float2bfloat16(v0));
                const float h1 = __bfloat162float(__float2bfloat16(v1));
                const float h2 = __bfloat162float(__float2bfloat16(v2));
                const float h3 = __bfloat162float(__float2bfloat16(v3));
                *(uint32_t*)&Ch[(size_t)r0 * ldc + col]       = pack_bf2(h0, h1);
                *(uint32_t*)&Ch[(size_t)(r0 + 8) * ldc + col] = pack_bf2(h2, h3);
                *(uint32_t*)&Cl[(size_t)r0 * ldc + col]       = pack_bf2(v0 - h0, v1 - h1);
                *(uint32_t*)&Cl[(size_t)(r0 + 8) * ldc + col] = pack_bf2(v2 - h2, v3 - h3);
            } else {  // OUT == 2: transposed split store C^T[col][row]
                const float vv[4] = {v0, v1, v2, v3};
#pragma unroll
                for (int e = 0; e < 4; ++e) {
                    const int cc = col + (e & 1);
                    const int rr = r0 + (e >> 1) * 8;
                    const __nv_bfloat16 hb = __float2bfloat16(vv[e]);
                    Ch[(size_t)cc * ldc + rr] = hb;
                    Cl[(size_t)cc * ldc + rr] =
                        __float2bfloat16(vv[e] - __bfloat162float(hb));
                }
            }
        }
    }
}

// ---------------------------------------------------------------------------
// Weight transpose + bf16 hi/lo split: W[l][K][N] -> hi/lo [l][N][K]
// ---------------------------------------------------------------------------
__global__ void conv_w(const float* __restrict__ W, __nv_bfloat16* __restrict__ hi,
                       __nv_bfloat16* __restrict__ lo, int K, int N)
{
    __shared__ float t[32][33];
    const int l = blockIdx.z;
    W  += (size_t)l * K * N;
    hi += (size_t)l * K * N;
    lo += (size_t)l * K * N;
    const int k0 = blockIdx.y * 32, n0 = blockIdx.x * 32;
    const int tx = threadIdx.x, ty = threadIdx.y;   // 32 x 8
#pragma unroll
    for (int i = ty; i < 32; i += 8)
        t[i][tx] = W[(size_t)(k0 + i) * N + n0 + tx];
    __syncthreads();
#pragma unroll
    for (int i = ty; i < 32; i += 8) {
        const float v = t[tx][i];
        const __nv_bfloat16 h = __float2bfloat16(v);
        const __nv_bfloat16 r = __float2bfloat16(v - __bfloat162float(h));
        hi[(size_t)(n0 + i) * K + k0 + tx] = h;
        lo[(size_t)(n0 + i) * K + k0 + tx] = r;
    }
}

// elementwise hi/lo split (for E)
__global__ void split_act(const float* __restrict__ x, __nv_bfloat16* __restrict__ hi,
                          __nv_bfloat16* __restrict__ lo, int n4)
{
    const int i = blockIdx.x * 256 + threadIdx.x;
    if (i >= n4) return;
    const float4 v = ((const float4*)x)[i];
    const float f[4] = {v.x, v.y, v.z, v.w};
    unsigned short hh[4], ll[4];
#pragma unroll
    for (int j = 0; j < 4; j++) {
        const __nv_bfloat16 hb = __float2bfloat16(f[j]);
        const __nv_bfloat16 lb = __float2bfloat16(f[j] - __bfloat162float(hb));
        hh[j] = __bfloat16_as_ushort(hb);
        ll[j] = __bfloat16_as_ushort(lb);
    }
    ((uint2*)hi)[i] = *(const uint2*)hh;
    ((uint2*)lo)[i] = *(const uint2*)ll;
}

// ---------------------------------------------------------------------------
// Sinusoid rate + embedding (writes split bf16 directly)
// ---------------------------------------------------------------------------
__global__ void rate_kernel(float* __restrict__ rate)
{
    const int d = blockIdx.x * 256 + threadIdx.x;
    if (d >= DD) return;
    const double LN1E4 = 9.210340371976184;
    const int par = d & 1;
    const float r1 = (float)exp(-LN1E4 * (double)d   / 1024.0);
    const float r2 = (float)exp( LN1E4 * (double)par / 1024.0);
    rate[d] = r1 * r2;
}

__global__ void embed_split(const int* __restrict__ x,
                            const float* __restrict__ emb,
                            const float* __restrict__ rate,
                            __nv_bfloat16* __restrict__ oh,
                            __nv_bfloat16* __restrict__ ol)
{
    const int bs = blockIdx.x;
    const int s  = bs & (SS - 1);
    const int tok = x[bs];
    const float* e = emb + (size_t)tok * DD;
    for (int d = threadIdx.x; d < DD; d += blockDim.x) {
        const int par = d & 1;
        const float ph = (float)s * rate[d] + 1.5707964f * (float)par;
        const float v = e[d] * 32.0f + sinf(ph);
        const __nv_bfloat16 hb = __float2bfloat16(v);
        oh[(size_t)bs * DD + d] = hb;
        ol[(size_t)bs * DD + d] = __float2bfloat16(v - __bfloat162float(hb));
    }
}

// ---------------------------------------------------------------------------
// Fused Srel gather + scale + masks + softmax; writes SPLIT bf16 aw.
// Zero-pads each row out to the next 256 boundary (AV reads <=128 boundary).
// ---------------------------------------------------------------------------
__global__ __launch_bounds__(256)
void attn_softmax(const float* __restrict__ lg, const float* __restrict__ qe,
                  const int* __restrict__ x,
                  __nv_bfloat16* __restrict__ awh, __nv_bfloat16* __restrict__ awl)
{
    const int i  = blockIdx.x;
    const int bh = blockIdx.y;
    const int b  = bh >> 4;
    const float* row  = lg + (size_t)bh * SS * SS + (size_t)i * SS;
    const float* qrow = qe + (size_t)bh * SS * SS + (size_t)i * SS;
    __nv_bfloat16* oh = awh + (size_t)bh * SS * SS + (size_t)i * SS;
    __nv_bfloat16* ol = awl + (size_t)bh * SS * SS + (size_t)i * SS;
    const int* xb = x + b * SS;
    const int t = threadIdx.x;
    const int nch = (i >> 8) + 1;

    float vals[4];
    float mx = -1e30f;
    for (int c = 0; c < nch; c++) {
        const int j = c * 256 + t;
        float vv = -1e30f;
        if (j <= i) {
            vv = (row[j] + qrow[SS - 1 - i + j]) * ATT_SCALE;
            if (xb[j] == 0) vv -= 1e9f;
        }
        vals[c] = vv;
        mx = fmaxf(mx, vv);
    }
    __shared__ float sh[8];
#pragma unroll
    for (int o = 16; o > 0; o >>= 1) mx = fmaxf(mx, __shfl_xor_sync(0xffffffffu, mx, o));
    if ((t & 31) == 0) sh[t >> 5] = mx;
    __syncthreads();
    mx = sh[0];
#pragma unroll
    for (int w = 1; w < 8; w++) mx = fmaxf(mx, sh[w]);

    float s = 0.f;
    for (int c = 0; c < nch; c++) { vals[c] = expf(vals[c] - mx); s += vals[c]; }
#pragma unroll
    for (int o = 16; o > 0; o >>= 1) s += __shfl_xor_sync(0xffffffffu, s, o);
    __syncthreads();
    if ((t & 31) == 0) sh[t >> 5] = s;
    __syncthreads();
    s = 0.f;
#pragma unroll
    for (int w = 0; w < 8; w++) s += sh[w];
    const float inv = 1.f / s;
    for (int c = 0; c < nch; c++) {
        const float p = vals[c] * inv;
        const __nv_bfloat16 hb = __float2bfloat16(p);
        oh[c * 256 + t] = hb;
        ol[c * 256 + t] = __float2bfloat16(p - __bfloat162float(hb));
    }
}

// ---------------------------------------------------------------------------
// LayerNorm over last dim (1024); reads fp32, writes SPLIT bf16.
// ---------------------------------------------------------------------------
__global__ __launch_bounds__(256)
void ln_split(const float* __restrict__ xin, const float* __restrict__ g,
              const float* __restrict__ be,
              __nv_bfloat16* __restrict__ oh, __nv_bfloat16* __restrict__ ol)
{
    const int row = blockIdx.x;
    const float* p = xin + (size_t)row * DD;
    const int t = threadIdx.x;
    float v[4];
    float s = 0.f, s2 = 0.f;
#pragma unroll
    for (int c = 0; c < 4; c++) {
        v[c] = p[t + c * 256];
        s += v[c];
        s2 += v[c] * v[c];
    }
    __shared__ float sh1[8], sh2[8];
#pragma unroll
    for (int o = 16; o > 0; o >>= 1) {
        s  += __shfl_xor_sync(0xffffffffu, s,  o);
        s2 += __shfl_xor_sync(0xffffffffu, s2, o);
    }
    if ((t & 31) == 0) { sh1[t >> 5] = s; sh2[t >> 5] = s2; }
    __syncthreads();
    s = 0.f; s2 = 0.f;
#pragma unroll
    for (int w = 0; w < 8; w++) { s += sh1[w]; s2 += sh2[w]; }
    const float mu  = s  * (1.f / DD);
    const float var = s2 * (1.f / DD) - mu * mu;
    const float inv = rsqrtf(var + 1e-6f);
#pragma unroll
    for (int c = 0; c < 4; c++) {
        const int d = t + c * 256;
        const float o = (v[c] - mu) * inv * g[d] + be[d];
        const __nv_bfloat16 hb = __float2bfloat16(o);
        oh[(size_t)row * DD + d] = hb;
        ol[(size_t)row * DD + d] = __float2bfloat16(o - __bfloat162float(hb));
    }
}

// ---------------------------------------------------------------------------
// Host side
// ---------------------------------------------------------------------------
using bf16 = __nv_bfloat16;

template<int BN, int SKIP, bool KCAP, int OUT, bool RELU>
static void run_mma(const bf16* ah, const bf16* al, const bf16* bh, const bf16* bl,
                    const float* bias, float* C, bf16* Ch, bf16* Cl,
                    int M, int N, int K, int lda, int ldb, int ldc,
                    int batch, int zdiv,
                    long long sA1, long long sA2,
                    long long sB1, long long sB2,
                    long long sC1, long long sC2)
{
    constexpr int STG = 2 * 10240 + 2 * BN * 80;
    static bool init = false;
    if (!init) {
        cudaFuncSetAttribute(gemm_mma<BN, SKIP, KCAP, OUT, RELU>,
                             cudaFuncAttributeMaxDynamicSharedMemorySize, 2 * STG);
        init = true;
    }
    dim3 grid(N / BN, M / 128, batch);
    gemm_mma<BN, SKIP, KCAP, OUT, RELU><<<grid, 256, 2 * STG>>>(
        ah, al, bh, bl, bias, C, Ch, Cl, K, lda, ldb, ldc,
        zdiv, sA1, sA2, sB1, sB2, sC1, sC2);
}

extern "C" void kernel_launch(void* const* d_in, const int* in_sizes, int n_in,
                              void* d_out, int out_size)
{
    const int*   x   = (const int*)  d_in[0];
    const float* emb = (const float*)d_in[1];
    const float* Wq  = (const float*)d_in[2];
    const float* bq  = (const float*)d_in[3];
    const float* Wk  = (const float*)d_in[4];
    const float* bk  = (const float*)d_in[5];
    const float* Wv  = (const float*)d_in[6];
    const float* bv  = (const float*)d_in[7];
    const float* Wo  = (const float*)d_in[8];
    const float* bo  = (const float*)d_in[9];
    const float* W1  = (const float*)d_in[10];
    const float* b1  = (const float*)d_in[11];
    const float* W2  = (const float*)d_in[12];
    const float* b2  = (const float*)d_in[13];
    const float* g1  = (const float*)d_in[14];
    const float* be1 = (const float*)d_in[15];
    const float* g2  = (const float*)d_in[16];
    const float* be2 = (const float*)d_in[17];
    const float* E   = (const float*)d_in[18];
    const float* Wf  = (const float*)d_in[19];
    const float* bf  = (const float*)d_in[20];
    float* out = (float*)d_out;

    float *t1, *h2, *qe, *lg, *rate;
    cudaGetSymbolAddress((void**)&t1, g_t1);
    cudaGetSymbolAddress((void**)&h2, g_h2);
    cudaGetSymbolAddress((void**)&qe, g_qe);
    cudaGetSymbolAddress((void**)&lg, g_lg);
    cudaGetSymbolAddress((void**)&rate, g_rate);

    bf16 *xh, *xl, *qh, *ql, *kh, *kl, *vth, *vtl, *ath, *atl, *ffh, *ffl;
    bf16 *awh, *awl, *eh, *el;
    cudaGetSymbolAddress((void**)&xh,  g_xh);  cudaGetSymbolAddress((void**)&xl,  g_xl);
    cudaGetSymbolAddress((void**)&qh,  g_qh);  cudaGetSymbolAddress((void**)&ql,  g_ql);
    cudaGetSymbolAddress((void**)&kh,  g_kh);  cudaGetSymbolAddress((void**)&kl,  g_kl);
    cudaGetSymbolAddress((void**)&vth, g_vth); cudaGetSymbolAddress((void**)&vtl, g_vtl);
    cudaGetSymbolAddress((void**)&ath, g_ath); cudaGetSymbolAddress((void**)&atl, g_atl);
    cudaGetSymbolAddress((void**)&ffh, g_ffh); cudaGetSymbolAddress((void**)&ffl, g_ffl);
    cudaGetSymbolAddress((void**)&awh, g_awh); cudaGetSymbolAddress((void**)&awl, g_awl);
    cudaGetSymbolAddress((void**)&eh,  g_eh);  cudaGetSymbolAddress((void**)&el,  g_el);

    bf16 *wqh, *wql, *wkh, *wkl, *wvh, *wvl, *woh, *wol;
    bf16 *w1h, *w1l, *w2h, *w2l, *wfh, *wfl;
    cudaGetSymbolAddress((void**)&wqh, g_wq_h); cudaGetSymbolAddress((void**)&wql, g_wq_l);
    cudaGetSymbolAddress((void**)&wkh, g_wk_h); cudaGetSymbolAddress((void**)&wkl, g_wk_l);
    cudaGetSymbolAddress((void**)&wvh, g_wv_h); cudaGetSymbolAddress((void**)&wvl, g_wv_l);
    cudaGetSymbolAddress((void**)&woh, g_wo_h); cudaGetSymbolAddress((void**)&wol, g_wo_l);
    cudaGetSymbolAddress((void**)&w1h, g_w1_h); cudaGetSymbolAddress((void**)&w1l, g_w1_l);
    cudaGetSymbolAddress((void**)&w2h, g_w2_h); cudaGetSymbolAddress((void**)&w2l, g_w2_l);
    cudaGetSymbolAddress((void**)&wfh, g_wf_h); cudaGetSymbolAddress((void**)&wfl, g_wf_l);

    const int M = BB * SS;  // 2048
    const long long sSD  = (long long)SS * DD;
    const long long sHSS = (long long)HH * SS * SS;
    const long long sSSq = (long long)SS * SS;
    const long long sDS  = (long long)DD * SS;

    // weight + E conversion
    {
        dim3 tb(32, 8);
        conv_w<<<dim3(DD / 32, DD / 32, LL), tb>>>(Wq, wqh, wql, DD, DD);
        conv_w<<<dim3(DD / 32, DD / 32, LL), tb>>>(Wk, wkh, wkl, DD, DD);
        conv_w<<<dim3(DD / 32, DD / 32, LL), tb>>>(Wv, wvh, wvl, DD, DD);
        conv_w<<<dim3(DD / 32, DD / 32, LL), tb>>>(Wo, woh, wol, DD, DD);
        conv_w<<<dim3(DF / 32, DD / 32, LL), tb>>>(W1, w1h, w1l, DD, DF);
        conv_w<<<dim3(DD / 32, DF / 32, LL), tb>>>(W2, w2h, w2l, DF, DD);
        conv_w<<<dim3(VV / 32, DD / 32, 1),  tb>>>(Wf, wfh, wfl, DD, VV);
        split_act<<<(LL * SS * HD / 4 + 255) / 256, 256>>>(E, eh, el, LL * SS * HD / 4);
    }

    rate_kernel<<<4, 256>>>(rate);
    embed_split<<<BB * SS, 256>>>(x, emb, rate, xh, xl);

    for (int l = 0; l < LL; l++) {
        const size_t wdd = (size_t)l * DD * DD;
        const size_t wdf = (size_t)l * DF * DD;
        const bf16* ehl = eh + (size_t)l * SS * HD;
        const bf16* ell = el + (size_t)l * SS * HD;

        // QKV projections (tensor cores); q,k split; v split-transposed per batch
        run_mma<128, 0, false, 1, false>(xh, xl, wqh + wdd, wql + wdd, bq + l * DD,
                                         nullptr, qh, ql, M, DD, DD, DD, DD, DD,
                                         1, 1, 0, 0, 0, 0, 0, 0);
        run_mma<128, 0, false, 1, false>(xh, xl, wkh + wdd, wkl + wdd, bk + l * DD,
                                         nullptr, kh, kl, M, DD, DD, DD, DD, DD,
                                         1, 1, 0, 0, 0, 0, 0, 0);
        run_mma<128, 0, false, 2, false>(xh, xl, wvh + wdd, wvl + wdd, bv + l * DD,
                                         nullptr, vth, vtl, SS, DD, DD, DD, DD, SS,
                                         BB, 1, sSD, 0, 0, 0, sDS, 0);

        // QE = q @ E^T  (anti-diagonal tiles only)
        run_mma<128, 1, false, 0, false>(qh, ql, ehl, ell, nullptr, qe, nullptr, nullptr,
                                         SS, SS, HD, DD, HD, SS, BB * HH, HH,
                                         sSD, HD, 0, 0, sHSS, sSSq);
        // QK^T (causal tiles only)
        run_mma<128, 2, false, 0, false>(qh, ql, kh, kl, nullptr, lg, nullptr, nullptr,
                                         SS, SS, HD, DD, DD, SS, BB * HH, HH,
                                         sSD, HD, sSD, HD, sHSS, sSSq);

        // fused skew + masks + softmax -> split bf16 aw
        attn_softmax<<<dim3(SS, BB * HH), 256>>>(lg, qe, x, awh, awl);

        // attn = aw @ v  (K capped, split output into ath/atl)
        run_mma<64, 0, true, 1, false>(awh, awl, vth, vtl, nullptr,
                                       nullptr, ath, atl, SS, HD, SS, SS, SS, DD,
                                       BB * HH, HH, sHSS, sSSq,
                                       sDS, (long long)HD * SS, sSD, HD);

        // Wo + LN1
        run_mma<128, 0, false, 0, false>(ath, atl, woh + wdd, wol + wdd, bo + l * DD,
                                         t1, nullptr, nullptr, M, DD, DD, DD, DD, DD,
                                         1, 1, 0, 0, 0, 0, 0, 0);
        ln_split<<<BB * SS, 256>>>(t1, g1 + l * DD, be1 + l * DD, xh, xl);

        // FFN
        run_mma<128, 0, false, 1, true>(xh, xl, w1h + wdf, w1l + wdf, b1 + l * DF,
                                        nullptr, ffh, ffl, M, DF, DD, DD, DD, DF,
                                        1, 1, 0, 0, 0, 0, 0, 0);
        run_mma<128, 0, false, 0, false>(ffh, ffl, w2h + wdf, w2l + wdf, b2 + l * DD,
                                         h2, nullptr, nullptr, M, DD, DF, DF, DF, DD,
                                         1, 1, 0, 0, 0, 0, 0, 0);
        ln_split<<<BB * SS, 256>>>(h2, g2 + l * DD, be2 + l * DD, xh, xl);
    }

    // final projection to vocab
    run_mma<128, 0, false, 0, false>(xh, xl, wfh, wfl, bf, out, nullptr, nullptr,
                                     M, VV, DD, DD, DD, VV, 1, 1, 0, 0, 0, 0, 0, 0);
}